// round 3
// baseline (speedup 1.0000x reference)
#include <cuda_runtime.h>
#include <cuda_bf16.h>
#include <stdint.h>

typedef unsigned long long u64;

#define QNUM 10000
#define DNUM 64
#define MNUM 50
#define BNUM 64
#define TNUM 512
#define NGRP 4

// ---------------- static scratch (no allocations allowed) ----------------
__device__ float g_w  [QNUM * MNUM];                        // softmax weights per question id
__device__ float g_kf [QNUM * DNUM];                        // k-half of f-MLP + bias, per question id
__device__ float g_e  [2 * QNUM * DNUM];                    // sigmoid erase per x id
__device__ float g_a  [2 * QNUM * DNUM];                    // tanh add per x id
__device__ float g_em [BNUM * TNUM * DNUM];                 // -e*mask stream per (b,t,d)
__device__ float g_am [BNUM * TNUM * DNUM];                 // a*mask stream
__device__ float g_w2f[NGRP * BNUM * TNUM * 32];            // (w,w) pairs, 16 slots/group, zero padded
__device__ float g_part[(size_t)NGRP * BNUM * (TNUM - 1) * DNUM];  // partial reads per m-group

// ---------------- f32x2 helpers ----------------
__device__ __forceinline__ u64 f2pk(float a, float b) {
    u64 r; asm("mov.b64 %0,{%1,%2};" : "=l"(r) : "f"(a), "f"(b)); return r;
}
__device__ __forceinline__ u64 f2bc(float a) {
    u64 r; asm("mov.b64 %0,{%1,%1};" : "=l"(r) : "f"(a)); return r;
}
__device__ __forceinline__ void f2up(u64 v, float& a, float& b) {
    asm("mov.b64 {%0,%1},%2;" : "=f"(a), "=f"(b) : "l"(v));
}
__device__ __forceinline__ u64 f2fma(u64 a, u64 b, u64 c) {
    u64 d; asm("fma.rn.f32x2 %0,%1,%2,%3;" : "=l"(d) : "l"(a), "l"(b), "l"(c)); return d;
}
__device__ __forceinline__ u64 f2mul(u64 a, u64 b) {
    u64 d; asm("mul.rn.f32x2 %0,%1,%2;" : "=l"(d) : "l"(a), "l"(b)); return d;
}

__device__ __forceinline__ float sigfast(float x) {
    return __fdividef(1.f, 1.f + __expf(-x));
}
__device__ __forceinline__ float tanhfast(float x) {
    x = fminf(fmaxf(x, -10.f), 10.f);
    float t = __expf(2.f * x);
    return (t - 1.f) * __fdividef(1.f, t + 1.f);
}

// ---------------- cp.async helpers ----------------
__device__ __forceinline__ void cpa16(uint32_t dst, const void* src) {
    asm volatile("cp.async.ca.shared.global [%0], [%1], 16;\n" :: "r"(dst), "l"(src));
}
__device__ __forceinline__ void cpcommit() { asm volatile("cp.async.commit_group;\n"); }
template <int N> __device__ __forceinline__ void cpwait() {
    asm volatile("cp.async.wait_group %0;\n" :: "n"(N));
}

// =====================================================================
// K1: per-question softmax weights + kf table  (10000 rows, 8 warps/block)
// =====================================================================
__global__ void __launch_bounds__(256) k_build_wkf(
    const float* __restrict__ k_emb, const float* __restrict__ Mk,
    const float* __restrict__ fW, const float* __restrict__ fb)
{
    __shared__ __align__(16) float sMkT[64 * 64];   // [i][m], zero-padded m>=50
    __shared__ __align__(16) float sfW2[64 * 64];   // f_W rows 64..127
    __shared__ float sfb[64];

    int tid = threadIdx.x;
    for (int idx = tid; idx < 4096; idx += 256) {
        int i = idx >> 6, m = idx & 63;
        sMkT[idx] = (m < MNUM) ? Mk[m * 64 + i] : 0.f;
        sfW2[idx] = fW[64 * 64 + idx];
    }
    if (tid < 64) sfb[tid] = fb[tid];
    __syncthreads();

    int q = blockIdx.x * 8 + (tid >> 5);
    int lane = tid & 31;

    float k0 = k_emb[q * 64 + lane];
    float k1 = k_emb[q * 64 + 32 + lane];

    // logits: m = lane, m = 32+lane (valid lane<18)
    float acc0 = 0.f, acc1 = 0.f;
#pragma unroll
    for (int i = 0; i < 64; i++) {
        float kv = __shfl_sync(0xffffffffu, (i < 32) ? k0 : k1, i & 31);
        acc0 += kv * sMkT[i * 64 + lane];
        acc1 += kv * sMkT[i * 64 + 32 + lane];
    }
    float v1 = (lane < 18) ? acc1 : -3.0e38f;
    float mx = fmaxf(acc0, v1);
#pragma unroll
    for (int d = 16; d >= 1; d >>= 1) mx = fmaxf(mx, __shfl_xor_sync(0xffffffffu, mx, d));
    float e0 = __expf(acc0 - mx);
    float e1 = (lane < 18) ? __expf(acc1 - mx) : 0.f;
    float sm = e0 + e1;
#pragma unroll
    for (int d = 16; d >= 1; d >>= 1) sm += __shfl_xor_sync(0xffffffffu, sm, d);
    float inv = __fdividef(1.f, sm);
    g_w[q * MNUM + lane] = e0 * inv;
    if (lane < 18) g_w[q * MNUM + 32 + lane] = e1 * inv;

    // kf = k @ fW2 + f_b   (thread owns d-pair)
    u64 acc = f2pk(sfb[2 * lane], sfb[2 * lane + 1]);
    const u64* W2 = (const u64*)sfW2;
#pragma unroll
    for (int i = 0; i < 64; i++) {
        float kv = __shfl_sync(0xffffffffu, (i < 32) ? k0 : k1, i & 31);
        acc = f2fma(f2bc(kv), W2[i * 32 + lane], acc);
    }
    *(u64*)&g_kf[q * 64 + 2 * lane] = acc;
}

// =====================================================================
// K2: e/a tables over 20000 v_emb rows (4 rows per warp)
// =====================================================================
__global__ void __launch_bounds__(256) k_build_ea(
    const float* __restrict__ v_emb,
    const float* __restrict__ eW, const float* __restrict__ eb,
    const float* __restrict__ aW, const float* __restrict__ ab)
{
    __shared__ __align__(16) float sWe[64 * 64];
    __shared__ __align__(16) float sWa[64 * 64];
    __shared__ float seb[64], sab[64];

    int tid = threadIdx.x;
    for (int idx = tid; idx < 4096; idx += 256) {
        sWe[idx] = eW[idx];
        sWa[idx] = aW[idx];
    }
    if (tid < 64) { seb[tid] = eb[tid]; sab[tid] = ab[tid]; }
    __syncthreads();

    int w = tid >> 5, lane = tid & 31;
    int r0 = blockIdx.x * 32 + w * 4;

    float v0[4], v1[4];
#pragma unroll
    for (int r = 0; r < 4; r++) {
        v0[r] = v_emb[(r0 + r) * 64 + lane];
        v1[r] = v_emb[(r0 + r) * 64 + 32 + lane];
    }
    u64 ebp = f2pk(seb[2 * lane], seb[2 * lane + 1]);
    u64 abp = f2pk(sab[2 * lane], sab[2 * lane + 1]);
    u64 ea[4], aa[4];
#pragma unroll
    for (int r = 0; r < 4; r++) { ea[r] = ebp; aa[r] = abp; }

    const u64* We2 = (const u64*)sWe;
    const u64* Wa2 = (const u64*)sWa;
#pragma unroll
    for (int i = 0; i < 64; i++) {
        u64 wep = We2[i * 32 + lane];
        u64 wap = Wa2[i * 32 + lane];
#pragma unroll
        for (int r = 0; r < 4; r++) {
            float kv = __shfl_sync(0xffffffffu, (i < 32) ? v0[r] : v1[r], i & 31);
            u64 kv2 = f2bc(kv);
            ea[r] = f2fma(kv2, wep, ea[r]);
            aa[r] = f2fma(kv2, wap, aa[r]);
        }
    }
#pragma unroll
    for (int r = 0; r < 4; r++) {
        float x0, x1;
        f2up(ea[r], x0, x1);
        float2 ev = make_float2(sigfast(x0), sigfast(x1));
        *(float2*)&g_e[(size_t)(r0 + r) * 64 + 2 * lane] = ev;
        f2up(aa[r], x0, x1);
        float2 av = make_float2(tanhfast(x0), tanhfast(x1));
        *(float2*)&g_a[(size_t)(r0 + r) * 64 + 2 * lane] = av;
    }
}

// =====================================================================
// K3: gather tables into per-(b,t) streams, fold mask, pre-pack w pairs
// =====================================================================
__global__ void __launch_bounds__(256) k_gather(
    const int* __restrict__ question, const int* __restrict__ response,
    const float* __restrict__ mask)
{
    int w = threadIdx.x >> 5, lane = threadIdx.x & 31;
    int row = blockIdx.x * 8 + w;             // b*512 + t
    int q = question[row];
    int r = response[row];
    float mt = mask[row];
    int x = q + QNUM * r;

    float2 ev = *(const float2*)&g_e[(size_t)x * 64 + 2 * lane];
    float2 av = *(const float2*)&g_a[(size_t)x * 64 + 2 * lane];
    float2 em = make_float2(-ev.x * mt, -ev.y * mt);
    float2 am = make_float2(av.x * mt, av.y * mt);
    *(float2*)&g_em[(size_t)row * 64 + 2 * lane] = em;
    *(float2*)&g_am[(size_t)row * 64 + 2 * lane] = am;

    int b = row >> 9, t = row & 511;
#pragma unroll
    for (int jj = 0; jj < 2; jj++) {
        int j = lane + jj * 32;
        int g = j >> 4, ml = j & 15;
        int np = (g < 2) ? 13 : 12;
        int m0 = (g < 2) ? 13 * g : 26 + 12 * (g - 2);
        float val = (ml < np) ? g_w[q * MNUM + m0 + ml] : 0.f;
        *(float2*)&g_w2f[(((size_t)(g * 64 + b)) * 512 + t) * 32 + 2 * ml] = make_float2(val, val);
    }
}

// =====================================================================
// K4: sequential scan. 64 CTAs (one per b) x 4 warps (m-groups).
// Thread owns a d-pair; Mv in 13 f32x2 registers. cp.async staged streams.
// =====================================================================
__global__ void __launch_bounds__(128) k_scan(const float* __restrict__ Mv0)
{
    __shared__ __align__(16) u64 smw[3][NGRP][8][16];
    __shared__ __align__(16) u64 sme[3][8][32];
    __shared__ __align__(16) u64 sma[3][8][32];

    int b = blockIdx.x;
    int g = threadIdx.x >> 5, lane = threadIdx.x & 31;
    int np = (g < 2) ? 13 : 12;
    int m0 = (g < 2) ? 13 * g : 26 + 12 * (g - 2);

    // init Mv (zero-padded slot for g>=2 is a no-op thanks to zero w)
    u64 mv[13];
#pragma unroll
    for (int p = 0; p < 13; p++) {
        if (p < np) {
            float2 v = *(const float2*)&Mv0[(m0 + p) * 64 + 2 * lane];
            mv[p] = f2pk(v.x, v.y);
        } else {
            mv[p] = 0ull;
        }
    }

    const char* wsrc0 = (const char*)g_w2f + ((size_t)(g * 64 + b)) * 512 * 32 * 4;
    const char* esrc0 = (const char*)g_em + ((size_t)b) * 512 * 64 * 4;
    const char* asrc0 = (const char*)g_am + ((size_t)b) * 512 * 64 * 4;

    // issue loads for 8-step block kb into buffer kb%3
    auto issue = [&](int kb) {
        int buf = kb % 3;
        size_t off = (size_t)kb * 8 * 128;    // 8 steps * 16 pairs * 8B
        uint32_t wd = (uint32_t)__cvta_generic_to_shared(&smw[buf][g][0][0]);
        cpa16(wd + lane * 16, wsrc0 + off + lane * 16);
        cpa16(wd + 512 + lane * 16, wsrc0 + off + 512 + lane * 16);
        if (g == 0) {
            size_t eoff = (size_t)kb * 8 * 256;   // 8 steps * 64 floats * 4B
            uint32_t ed = (uint32_t)__cvta_generic_to_shared(&sme[buf][0][0]);
            uint32_t ad = (uint32_t)__cvta_generic_to_shared(&sma[buf][0][0]);
#pragma unroll
            for (int k = 0; k < 4; k++) {
                cpa16(ed + k * 512 + lane * 16, esrc0 + eoff + k * 512 + lane * 16);
                cpa16(ad + k * 512 + lane * 16, asrc0 + eoff + k * 512 + lane * 16);
            }
        }
    };

    issue(0); cpcommit();
    issue(1); cpcommit();
    issue(2); cpcommit();

    float* partbase = g_part + ((size_t)(g * 64 + b)) * 511 * 64 + 2 * lane;

    for (int kb = 0; kb < 64; kb++) {
        cpwait<2>();
        __syncthreads();
        int buf = kb % 3;
#pragma unroll
        for (int s = 0; s < 8; s++) {
            u64 em2 = sme[buf][s][lane];
            u64 am2 = sma[buf][s][lane];
            const u64* wrow = &smw[buf][g][s][0];
            if (kb | s) {   // t > 0: read before update
                u64 acc = f2mul(wrow[0], mv[0]);
#pragma unroll
                for (int p = 1; p < 13; p++) acc = f2fma(wrow[p], mv[p], acc);
                int t = kb * 8 + s;
                *(u64*)(partbase + (size_t)(t - 1) * 64) = acc;
            }
#pragma unroll
            for (int p = 0; p < 13; p++) {
                u64 tmp = f2fma(em2, mv[p], am2);      // mt*(a - e*Mv)
                mv[p] = f2fma(wrow[p], tmp, mv[p]);    // Mv += w * tmp
            }
        }
        __syncthreads();
        if (kb + 3 < 64) issue(kb + 3);
        cpcommit();
    }
}

// =====================================================================
// K5: head: sum partials -> read, f = tanh(read@fW1 + kf), p = f.pW + pb
// =====================================================================
__global__ void __launch_bounds__(256) k_head(
    const int* __restrict__ question, const float* __restrict__ fW,
    const float* __restrict__ pW, const float* __restrict__ pb,
    float* __restrict__ out)
{
    __shared__ __align__(16) float sfW1[64 * 64];
    __shared__ float spw[64];

    int tid = threadIdx.x;
    for (int idx = tid; idx < 4096; idx += 256) sfW1[idx] = fW[idx];
    if (tid < 64) spw[tid] = pW[tid];
    __syncthreads();

    int w = tid >> 5, lane = tid & 31;
    int row = blockIdx.x * 8 + w;          // 0..32703
    int b = row / 511;
    int tp = row - b * 511;                // output index, original t = tp+1
    int q = question[b * 512 + tp + 1];

    float2 rd = make_float2(0.f, 0.f);
#pragma unroll
    for (int g = 0; g < NGRP; g++) {
        float2 v = *(const float2*)&g_part[(((size_t)(g * 64 + b)) * 511 + tp) * 64 + 2 * lane];
        rd.x += v.x; rd.y += v.y;
    }
    float2 kf2 = *(const float2*)&g_kf[(size_t)q * 64 + 2 * lane];
    u64 facc = f2pk(kf2.x, kf2.y);
    const u64* W1 = (const u64*)sfW1;
    float r0 = rd.x, r1 = rd.y;
#pragma unroll
    for (int i = 0; i < 64; i++) {
        float rv = __shfl_sync(0xffffffffu, (i & 1) ? r1 : r0, i >> 1);
        facc = f2fma(f2bc(rv), W1[i * 32 + lane], facc);
    }
    float f0, f1;
    f2up(facc, f0, f1);
    f0 = tanhfast(f0);
    f1 = tanhfast(f1);
    float s = f0 * spw[2 * lane] + f1 * spw[2 * lane + 1];
#pragma unroll
    for (int d = 16; d >= 1; d >>= 1) s += __shfl_xor_sync(0xffffffffu, s, d);
    if (lane == 0) out[row] = s + pb[0];
}

// =====================================================================
extern "C" void kernel_launch(void* const* d_in, const int* in_sizes, int n_in,
                              void* d_out, int out_size)
{
    const int*   question = (const int*)d_in[0];
    const int*   response = (const int*)d_in[1];
    const float* mask     = (const float*)d_in[2];
    const float* k_emb    = (const float*)d_in[3];
    const float* v_emb    = (const float*)d_in[4];
    const float* Mk       = (const float*)d_in[5];
    const float* Mv0      = (const float*)d_in[6];
    const float* e_W      = (const float*)d_in[7];
    const float* e_b      = (const float*)d_in[8];
    const float* a_W      = (const float*)d_in[9];
    const float* a_b      = (const float*)d_in[10];
    const float* f_W      = (const float*)d_in[11];
    const float* f_b      = (const float*)d_in[12];
    const float* p_W      = (const float*)d_in[13];
    const float* p_b      = (const float*)d_in[14];
    float* out = (float*)d_out;

    k_build_wkf<<<QNUM / 8, 256>>>(k_emb, Mk, f_W, f_b);
    k_build_ea<<<2 * QNUM / 32, 256>>>(v_emb, e_W, e_b, a_W, a_b);
    k_gather<<<BNUM * TNUM / 8, 256>>>(question, response, mask);
    k_scan<<<BNUM, 128>>>(Mv0);
    k_head<<<BNUM * (TNUM - 1) / 8, 256>>>(question, f_W, p_W, p_b, out);

    (void)in_sizes; (void)n_in; (void)out_size;
}

// round 5
// speedup vs baseline: 1.2165x; 1.2165x over previous
#include <cuda_runtime.h>
#include <cuda_bf16.h>
#include <stdint.h>

typedef unsigned long long u64;

#define QNUM 10000
#define DNUM 64
#define MNUM 50
#define BNUM 64
#define TNUM 512
#define NGRP 8

// ---------------- static scratch (no allocations allowed) ----------------
__device__ float g_w  [QNUM * MNUM];                        // softmax weights per question id
__device__ float g_kf [QNUM * DNUM];                        // k-half of f-MLP + bias, per question id
__device__ float g_e  [2 * QNUM * DNUM];                    // sigmoid erase per x id
__device__ float g_a  [2 * QNUM * DNUM];                    // tanh add per x id
__device__ float g_em [BNUM * TNUM * DNUM];                 // -e*mask stream per (b,t,d)
__device__ float g_am [BNUM * TNUM * DNUM];                 // a*mask stream
__device__ float g_w2f[NGRP * BNUM * TNUM * 16];            // (w,w) pairs, 8 slots/group, zero padded
__device__ float g_read[(size_t)BNUM * (TNUM - 1) * DNUM];  // fully reduced read vectors

// ---------------- f32x2 helpers ----------------
__device__ __forceinline__ u64 f2pk(float a, float b) {
    u64 r; asm("mov.b64 %0,{%1,%2};" : "=l"(r) : "f"(a), "f"(b)); return r;
}
__device__ __forceinline__ u64 f2bc(float a) {
    u64 r; asm("mov.b64 %0,{%1,%1};" : "=l"(r) : "f"(a)); return r;
}
__device__ __forceinline__ void f2up(u64 v, float& a, float& b) {
    asm("mov.b64 {%0,%1},%2;" : "=f"(a), "=f"(b) : "l"(v));
}
__device__ __forceinline__ u64 f2fma(u64 a, u64 b, u64 c) {
    u64 d; asm("fma.rn.f32x2 %0,%1,%2,%3;" : "=l"(d) : "l"(a), "l"(b), "l"(c)); return d;
}
__device__ __forceinline__ u64 f2mul(u64 a, u64 b) {
    u64 d; asm("mul.rn.f32x2 %0,%1,%2;" : "=l"(d) : "l"(a), "l"(b)); return d;
}
__device__ __forceinline__ u64 f2add(u64 a, u64 b) {
    u64 d; asm("add.rn.f32x2 %0,%1,%2;" : "=l"(d) : "l"(a), "l"(b)); return d;
}

__device__ __forceinline__ float sigfast(float x) {
    return __fdividef(1.f, 1.f + __expf(-x));
}
__device__ __forceinline__ float tanhfast(float x) {
    x = fminf(fmaxf(x, -10.f), 10.f);
    float t = __expf(2.f * x);
    return (t - 1.f) * __fdividef(1.f, t + 1.f);
}

// ---------------- cp.async helpers ----------------
__device__ __forceinline__ void cpa16(uint32_t dst, const void* src) {
    asm volatile("cp.async.ca.shared.global [%0], [%1], 16;\n" :: "r"(dst), "l"(src));
}
__device__ __forceinline__ void cpcommit() { asm volatile("cp.async.commit_group;\n"); }
template <int N> __device__ __forceinline__ void cpwait() {
    asm volatile("cp.async.wait_group %0;\n" :: "n"(N));
}

// =====================================================================
// K1: merged precompute.
//   blocks [0,1250): per-question softmax weights + kf table (8 q/block)
//   blocks [1250,1875): e/a tables over 20000 v_emb rows (32 rows/block)
// =====================================================================
__global__ void __launch_bounds__(256) k_build(
    const float* __restrict__ k_emb, const float* __restrict__ Mk,
    const float* __restrict__ fW, const float* __restrict__ fb,
    const float* __restrict__ v_emb,
    const float* __restrict__ eW, const float* __restrict__ eb,
    const float* __restrict__ aW, const float* __restrict__ ab)
{
    __shared__ __align__(16) float sA[64 * 64];
    __shared__ __align__(16) float sB[64 * 64];
    __shared__ float sb0[64], sb1[64];

    int tid = threadIdx.x;
    int w = tid >> 5, lane = tid & 31;

    if (blockIdx.x < 1250) {
        // -------- wkf path --------
        for (int idx = tid; idx < 4096; idx += 256) {
            int i = idx >> 6, m = idx & 63;
            sA[idx] = (m < MNUM) ? Mk[m * 64 + i] : 0.f;   // MkT [i][m]
            sB[idx] = fW[64 * 64 + idx];                    // fW rows 64..127
        }
        if (tid < 64) sb0[tid] = fb[tid];
        __syncthreads();

        int q = blockIdx.x * 8 + w;

        float k0 = k_emb[q * 64 + lane];
        float k1 = k_emb[q * 64 + 32 + lane];

        float acc0 = 0.f, acc1 = 0.f;
#pragma unroll
        for (int i = 0; i < 64; i++) {
            float kv = __shfl_sync(0xffffffffu, (i < 32) ? k0 : k1, i & 31);
            acc0 += kv * sA[i * 64 + lane];
            acc1 += kv * sA[i * 64 + 32 + lane];
        }
        float v1 = (lane < 18) ? acc1 : -3.0e38f;
        float mx = fmaxf(acc0, v1);
#pragma unroll
        for (int d = 16; d >= 1; d >>= 1) mx = fmaxf(mx, __shfl_xor_sync(0xffffffffu, mx, d));
        float e0 = __expf(acc0 - mx);
        float e1 = (lane < 18) ? __expf(acc1 - mx) : 0.f;
        float sm = e0 + e1;
#pragma unroll
        for (int d = 16; d >= 1; d >>= 1) sm += __shfl_xor_sync(0xffffffffu, sm, d);
        float inv = __fdividef(1.f, sm);
        g_w[q * MNUM + lane] = e0 * inv;
        if (lane < 18) g_w[q * MNUM + 32 + lane] = e1 * inv;

        u64 acc = f2pk(sb0[2 * lane], sb0[2 * lane + 1]);
        const u64* W2 = (const u64*)sB;
#pragma unroll
        for (int i = 0; i < 64; i++) {
            float kv = __shfl_sync(0xffffffffu, (i < 32) ? k0 : k1, i & 31);
            acc = f2fma(f2bc(kv), W2[i * 32 + lane], acc);
        }
        *(u64*)&g_kf[q * 64 + 2 * lane] = acc;
    } else {
        // -------- e/a path --------
        for (int idx = tid; idx < 4096; idx += 256) {
            sA[idx] = eW[idx];
            sB[idx] = aW[idx];
        }
        if (tid < 64) { sb0[tid] = eb[tid]; sb1[tid] = ab[tid]; }
        __syncthreads();

        int r0 = (blockIdx.x - 1250) * 32 + w * 4;

        float v0[4], v1[4];
#pragma unroll
        for (int r = 0; r < 4; r++) {
            v0[r] = v_emb[(r0 + r) * 64 + lane];
            v1[r] = v_emb[(r0 + r) * 64 + 32 + lane];
        }
        u64 ebp = f2pk(sb0[2 * lane], sb0[2 * lane + 1]);
        u64 abp = f2pk(sb1[2 * lane], sb1[2 * lane + 1]);
        u64 ea[4], aa[4];
#pragma unroll
        for (int r = 0; r < 4; r++) { ea[r] = ebp; aa[r] = abp; }

        const u64* We2 = (const u64*)sA;
        const u64* Wa2 = (const u64*)sB;
#pragma unroll
        for (int i = 0; i < 64; i++) {
            u64 wep = We2[i * 32 + lane];
            u64 wap = Wa2[i * 32 + lane];
#pragma unroll
            for (int r = 0; r < 4; r++) {
                float kv = __shfl_sync(0xffffffffu, (i < 32) ? v0[r] : v1[r], i & 31);
                u64 kv2 = f2bc(kv);
                ea[r] = f2fma(kv2, wep, ea[r]);
                aa[r] = f2fma(kv2, wap, aa[r]);
            }
        }
#pragma unroll
        for (int r = 0; r < 4; r++) {
            float x0, x1;
            f2up(ea[r], x0, x1);
            *(float2*)&g_e[(size_t)(r0 + r) * 64 + 2 * lane] = make_float2(sigfast(x0), sigfast(x1));
            f2up(aa[r], x0, x1);
            *(float2*)&g_a[(size_t)(r0 + r) * 64 + 2 * lane] = make_float2(tanhfast(x0), tanhfast(x1));
        }
    }
}

// =====================================================================
// K2: gather tables into per-(b,t) streams, fold mask, pre-pack w pairs
// =====================================================================
__global__ void __launch_bounds__(256) k_gather(
    const int* __restrict__ question, const int* __restrict__ response,
    const float* __restrict__ mask)
{
    int w = threadIdx.x >> 5, lane = threadIdx.x & 31;
    int row = blockIdx.x * 8 + w;             // b*512 + t
    int q = question[row];
    int r = response[row];
    float mt = mask[row];
    int x = q + QNUM * r;

    float2 ev = *(const float2*)&g_e[(size_t)x * 64 + 2 * lane];
    float2 av = *(const float2*)&g_a[(size_t)x * 64 + 2 * lane];
    *(float2*)&g_em[(size_t)row * 64 + 2 * lane] = make_float2(-ev.x * mt, -ev.y * mt);
    *(float2*)&g_am[(size_t)row * 64 + 2 * lane] = make_float2(av.x * mt, av.y * mt);

    int b = row >> 9, t = row & 511;
#pragma unroll
    for (int jj = 0; jj < 2; jj++) {
        int j = lane + jj * 32;               // 0..63 = 8 groups x 8 slots
        int g = j >> 3, sl = j & 7;
        int np = (g < 2) ? 7 : 6;
        int m0 = (g < 2) ? 7 * g : 14 + 6 * (g - 2);
        float val = (sl < np) ? g_w[q * MNUM + m0 + sl] : 0.f;
        *(float2*)&g_w2f[(((size_t)(g * 64 + b)) * 512 + t) * 16 + 2 * sl] = make_float2(val, val);
    }
}

// =====================================================================
// K3: sequential scan. 64 CTAs (one per b) x 8 warps (m-groups of <=7).
// Thread owns a d-pair column; Mv in 7 f32x2 registers. cp.async staged.
// Per 8-step block, group partial reads are reduced in shared memory and
// the fully-summed read vector goes straight to g_read.
// =====================================================================
__global__ void __launch_bounds__(256) k_scan(const float* __restrict__ Mv0)
{
    __shared__ __align__(16) u64 smw[3][NGRP][8][8];   // [buf][g][step][slot] 12KB
    __shared__ __align__(16) u64 sme[3][8][32];        // [buf][step][dpair]   6KB
    __shared__ __align__(16) u64 sma[3][8][32];        //                      6KB
    __shared__ __align__(16) u64 stag[NGRP][8][32];    // [g][step][dpair]    16KB

    int b = blockIdx.x;
    int tid = threadIdx.x;
    int g = tid >> 5, lane = tid & 31;
    int np = (g < 2) ? 7 : 6;
    int m0 = (g < 2) ? 7 * g : 14 + 6 * (g - 2);

    u64 mv[7];
#pragma unroll
    for (int p = 0; p < 7; p++)
        mv[p] = (p < np) ? *(const u64*)&Mv0[(m0 + p) * 64 + 2 * lane] : 0ull;

    // per-thread cp.async source/dest (w: all 256 threads; em: tid<128; am: tid>=128)
    const char* wsrc = (const char*)g_w2f + ((size_t)(g * 64 + b) * 512) * 64 + (size_t)lane * 16;
    int s8 = (tid >> 4) & 7, c8 = tid & 15;
    const char* easrc = (const char*)((tid < 128) ? g_em : g_am)
                      + (size_t)b * 512 * 256 + (size_t)s8 * 256 + (size_t)c8 * 16;

    uint32_t swdst = (uint32_t)__cvta_generic_to_shared(&smw[0][0][0][0]) + g * 512 + lane * 16;
    uint32_t eadst = (uint32_t)__cvta_generic_to_shared(
                         (tid < 128) ? &sme[0][0][0] : &sma[0][0][0]) + s8 * 256 + c8 * 16;

    auto issue = [&](int kb) {
        int buf = kb - (kb / 3) * 3;
        cpa16(swdst + buf * 4096, wsrc + (size_t)kb * 512);
        cpa16(eadst + buf * 2048, easrc + (size_t)kb * 2048);
    };

    issue(0); cpcommit();
    issue(1); cpcommit();
    issue(2); cpcommit();

    for (int kb = 0; kb < 64; kb++) {
        cpwait<2>();
        __syncthreads();
        int buf = kb - (kb / 3) * 3;
        const u64* wr = &smw[buf][g][0][0];
#pragma unroll
        for (int s = 0; s < 8; s++) {
            u64 em2 = sme[buf][s][lane];
            u64 am2 = sma[buf][s][lane];
            u64 w0 = wr[s * 8 + 0], w1 = wr[s * 8 + 1], w2 = wr[s * 8 + 2],
                w3 = wr[s * 8 + 3], w4 = wr[s * 8 + 4], w5 = wr[s * 8 + 5],
                w6 = wr[s * 8 + 6];
            // read (state before this step's update)
            u64 p0 = f2mul(w0, mv[0]);
            u64 p1 = f2mul(w1, mv[1]);
            p0 = f2fma(w2, mv[2], p0);
            p1 = f2fma(w3, mv[3], p1);
            p0 = f2fma(w4, mv[4], p0);
            p1 = f2fma(w5, mv[5], p1);
            p0 = f2fma(w6, mv[6], p0);
            stag[g][s][lane] = f2add(p0, p1);
            // update: Mv += w * (mt*(a - e*Mv))
            u64 t0;
            t0 = f2fma(em2, mv[0], am2); mv[0] = f2fma(w0, t0, mv[0]);
            t0 = f2fma(em2, mv[1], am2); mv[1] = f2fma(w1, t0, mv[1]);
            t0 = f2fma(em2, mv[2], am2); mv[2] = f2fma(w2, t0, mv[2]);
            t0 = f2fma(em2, mv[3], am2); mv[3] = f2fma(w3, t0, mv[3]);
            t0 = f2fma(em2, mv[4], am2); mv[4] = f2fma(w4, t0, mv[4]);
            t0 = f2fma(em2, mv[5], am2); mv[5] = f2fma(w5, t0, mv[5]);
            t0 = f2fma(em2, mv[6], am2); mv[6] = f2fma(w6, t0, mv[6]);
        }
        __syncthreads();
        // reduce 8 group partials -> g_read. warp g handles step s_o = g.
        if ((kb | g) != 0) {
            u64 a0 = f2add(stag[0][g][lane], stag[1][g][lane]);
            u64 a1 = f2add(stag[2][g][lane], stag[3][g][lane]);
            u64 a2 = f2add(stag[4][g][lane], stag[5][g][lane]);
            u64 a3 = f2add(stag[6][g][lane], stag[7][g][lane]);
            a0 = f2add(a0, a1);
            a2 = f2add(a2, a3);
            a0 = f2add(a0, a2);
            int tout = kb * 8 + g - 1;        // t-1 for t = kb*8+g
            *(u64*)&g_read[((size_t)b * 511 + tout) * 64 + 2 * lane] = a0;
        }
        if (kb + 3 < 64) issue(kb + 3);
        cpcommit();
    }
}

// =====================================================================
// K4: head: f = tanh(read@fW1 + kf), p = f.pW + pb.  4 rows per warp.
// =====================================================================
__global__ void __launch_bounds__(256) k_head(
    const int* __restrict__ question, const float* __restrict__ fW,
    const float* __restrict__ pW, const float* __restrict__ pb,
    float* __restrict__ out)
{
    __shared__ __align__(16) float sfW1[64 * 64];
    __shared__ float spw[64];

    int tid = threadIdx.x;
    for (int idx = tid; idx < 4096; idx += 256) sfW1[idx] = fW[idx];
    if (tid < 64) spw[tid] = pW[tid];
    __syncthreads();

    int w = tid >> 5, lane = tid & 31;
    int row0 = blockIdx.x * 32 + w * 4;        // 4 rows per warp, 32704 total

    float r0[4], r1[4];
    u64 facc[4];
#pragma unroll
    for (int j = 0; j < 4; j++) {
        int row = row0 + j;
        int b = row / 511;
        int tp = row - b * 511;
        int q = question[b * 512 + tp + 1];
        float2 rd = *(const float2*)&g_read[(size_t)row * 64 + 2 * lane];
        r0[j] = rd.x; r1[j] = rd.y;
        float2 kf2 = *(const float2*)&g_kf[(size_t)q * 64 + 2 * lane];
        facc[j] = f2pk(kf2.x, kf2.y);
    }

    const u64* W1 = (const u64*)sfW1;
#pragma unroll
    for (int i = 0; i < 64; i++) {
        u64 w1p = W1[i * 32 + lane];
#pragma unroll
        for (int j = 0; j < 4; j++) {
            float rv = __shfl_sync(0xffffffffu, (i & 1) ? r1[j] : r0[j], i >> 1);
            facc[j] = f2fma(f2bc(rv), w1p, facc[j]);
        }
    }

    float pw0 = spw[2 * lane], pw1 = spw[2 * lane + 1];
    float pbv = pb[0];
#pragma unroll
    for (int j = 0; j < 4; j++) {
        float f0, f1;
        f2up(facc[j], f0, f1);
        float s = tanhfast(f0) * pw0 + tanhfast(f1) * pw1;
#pragma unroll
        for (int d = 16; d >= 1; d >>= 1) s += __shfl_xor_sync(0xffffffffu, s, d);
        if (lane == 0) out[row0 + j] = s + pbv;
    }
}

// =====================================================================
extern "C" void kernel_launch(void* const* d_in, const int* in_sizes, int n_in,
                              void* d_out, int out_size)
{
    const int*   question = (const int*)d_in[0];
    const int*   response = (const int*)d_in[1];
    const float* mask     = (const float*)d_in[2];
    const float* k_emb    = (const float*)d_in[3];
    const float* v_emb    = (const float*)d_in[4];
    const float* Mk       = (const float*)d_in[5];
    const float* Mv0      = (const float*)d_in[6];
    const float* e_W      = (const float*)d_in[7];
    const float* e_b      = (const float*)d_in[8];
    const float* a_W      = (const float*)d_in[9];
    const float* a_b      = (const float*)d_in[10];
    const float* f_W      = (const float*)d_in[11];
    const float* f_b      = (const float*)d_in[12];
    const float* p_W      = (const float*)d_in[13];
    const float* p_b      = (const float*)d_in[14];
    float* out = (float*)d_out;

    k_build<<<1875, 256>>>(k_emb, Mk, f_W, f_b, v_emb, e_W, e_b, a_W, a_b);
    k_gather<<<BNUM * TNUM / 8, 256>>>(question, response, mask);
    k_scan<<<BNUM, 256>>>(Mv0);
    k_head<<<BNUM * (TNUM - 1) / 32, 256>>>(question, f_W, p_W, p_b, out);

    (void)in_sizes; (void)n_in; (void)out_size;
}

// round 6
// speedup vs baseline: 1.4168x; 1.1646x over previous
#include <cuda_runtime.h>
#include <cuda_bf16.h>
#include <stdint.h>

typedef unsigned long long u64;

#define QNUM 10000
#define DNUM 64
#define MNUM 50
#define BNUM 64
#define TNUM 512
#define NGRP 8
#define PART_STRIDE ((size_t)BNUM * (TNUM - 1) * DNUM)   // floats per partial stream

// ---------------- static scratch (no allocations allowed) ----------------
__device__ float g_w  [QNUM * MNUM];                        // softmax weights per question id
__device__ float g_kf [QNUM * DNUM];                        // k-half of f-MLP + bias, per question id
__device__ float g_e  [2 * QNUM * DNUM];                    // sigmoid erase per x id
__device__ float g_a  [2 * QNUM * DNUM];                    // tanh add per x id
__device__ float g_em [BNUM * TNUM * DNUM];                 // -e*mask stream per (b,t,d)
__device__ float g_am [BNUM * TNUM * DNUM];                 // a*mask stream
__device__ float g_w2f[NGRP * BNUM * TNUM * 16];            // (w,w) pairs, 8 slots/group, zero padded
__device__ __align__(16) float g_part[2 * PART_STRIDE];     // 2 partial read streams (split halves)

// ---------------- f32x2 helpers ----------------
__device__ __forceinline__ u64 f2pk(float a, float b) {
    u64 r; asm("mov.b64 %0,{%1,%2};" : "=l"(r) : "f"(a), "f"(b)); return r;
}
__device__ __forceinline__ u64 f2bc(float a) {
    u64 r; asm("mov.b64 %0,{%1,%1};" : "=l"(r) : "f"(a)); return r;
}
__device__ __forceinline__ void f2up(u64 v, float& a, float& b) {
    asm("mov.b64 {%0,%1},%2;" : "=f"(a), "=f"(b) : "l"(v));
}
__device__ __forceinline__ u64 f2fma(u64 a, u64 b, u64 c) {
    u64 d; asm("fma.rn.f32x2 %0,%1,%2,%3;" : "=l"(d) : "l"(a), "l"(b), "l"(c)); return d;
}
__device__ __forceinline__ u64 f2mul(u64 a, u64 b) {
    u64 d; asm("mul.rn.f32x2 %0,%1,%2;" : "=l"(d) : "l"(a), "l"(b)); return d;
}
__device__ __forceinline__ u64 f2add(u64 a, u64 b) {
    u64 d; asm("add.rn.f32x2 %0,%1,%2;" : "=l"(d) : "l"(a), "l"(b)); return d;
}

__device__ __forceinline__ float sigfast(float x) {
    return __fdividef(1.f, 1.f + __expf(-x));
}
__device__ __forceinline__ float tanhfast(float x) {
    x = fminf(fmaxf(x, -10.f), 10.f);
    float t = __expf(2.f * x);
    return (t - 1.f) * __fdividef(1.f, t + 1.f);
}

// ---------------- cp.async helpers ----------------
__device__ __forceinline__ void cpa16(uint32_t dst, const void* src) {
    asm volatile("cp.async.ca.shared.global [%0], [%1], 16;\n" :: "r"(dst), "l"(src));
}
__device__ __forceinline__ void cpcommit() { asm volatile("cp.async.commit_group;\n"); }
template <int N> __device__ __forceinline__ void cpwait() {
    asm volatile("cp.async.wait_group %0;\n" :: "n"(N));
}

// =====================================================================
// K1: merged precompute.
//   blocks [0,1250): per-question softmax weights + kf table (8 q/block)
//   blocks [1250,1875): e/a tables over 20000 v_emb rows (32 rows/block)
// =====================================================================
__global__ void __launch_bounds__(256) k_build(
    const float* __restrict__ k_emb, const float* __restrict__ Mk,
    const float* __restrict__ fW, const float* __restrict__ fb,
    const float* __restrict__ v_emb,
    const float* __restrict__ eW, const float* __restrict__ eb,
    const float* __restrict__ aW, const float* __restrict__ ab)
{
    __shared__ __align__(16) float sA[64 * 64];
    __shared__ __align__(16) float sB[64 * 64];
    __shared__ float sb0[64], sb1[64];

    int tid = threadIdx.x;
    int w = tid >> 5, lane = tid & 31;

    if (blockIdx.x < 1250) {
        // -------- wkf path --------
        for (int idx = tid; idx < 4096; idx += 256) {
            int i = idx >> 6, m = idx & 63;
            sA[idx] = (m < MNUM) ? Mk[m * 64 + i] : 0.f;   // MkT [i][m]
            sB[idx] = fW[64 * 64 + idx];                    // fW rows 64..127
        }
        if (tid < 64) sb0[tid] = fb[tid];
        __syncthreads();

        int q = blockIdx.x * 8 + w;

        float k0 = k_emb[q * 64 + lane];
        float k1 = k_emb[q * 64 + 32 + lane];

        float acc0 = 0.f, acc1 = 0.f;
#pragma unroll
        for (int i = 0; i < 64; i++) {
            float kv = __shfl_sync(0xffffffffu, (i < 32) ? k0 : k1, i & 31);
            acc0 += kv * sA[i * 64 + lane];
            acc1 += kv * sA[i * 64 + 32 + lane];
        }
        float v1 = (lane < 18) ? acc1 : -3.0e38f;
        float mx = fmaxf(acc0, v1);
#pragma unroll
        for (int d = 16; d >= 1; d >>= 1) mx = fmaxf(mx, __shfl_xor_sync(0xffffffffu, mx, d));
        float e0 = __expf(acc0 - mx);
        float e1 = (lane < 18) ? __expf(acc1 - mx) : 0.f;
        float sm = e0 + e1;
#pragma unroll
        for (int d = 16; d >= 1; d >>= 1) sm += __shfl_xor_sync(0xffffffffu, sm, d);
        float inv = __fdividef(1.f, sm);
        g_w[q * MNUM + lane] = e0 * inv;
        if (lane < 18) g_w[q * MNUM + 32 + lane] = e1 * inv;

        u64 acc = f2pk(sb0[2 * lane], sb0[2 * lane + 1]);
        const u64* W2 = (const u64*)sB;
#pragma unroll
        for (int i = 0; i < 64; i++) {
            float kv = __shfl_sync(0xffffffffu, (i < 32) ? k0 : k1, i & 31);
            acc = f2fma(f2bc(kv), W2[i * 32 + lane], acc);
        }
        *(u64*)&g_kf[q * 64 + 2 * lane] = acc;
    } else {
        // -------- e/a path --------
        for (int idx = tid; idx < 4096; idx += 256) {
            sA[idx] = eW[idx];
            sB[idx] = aW[idx];
        }
        if (tid < 64) { sb0[tid] = eb[tid]; sb1[tid] = ab[tid]; }
        __syncthreads();

        int r0 = (blockIdx.x - 1250) * 32 + w * 4;

        float v0[4], v1[4];
#pragma unroll
        for (int r = 0; r < 4; r++) {
            v0[r] = v_emb[(r0 + r) * 64 + lane];
            v1[r] = v_emb[(r0 + r) * 64 + 32 + lane];
        }
        u64 ebp = f2pk(sb0[2 * lane], sb0[2 * lane + 1]);
        u64 abp = f2pk(sb1[2 * lane], sb1[2 * lane + 1]);
        u64 ea[4], aa[4];
#pragma unroll
        for (int r = 0; r < 4; r++) { ea[r] = ebp; aa[r] = abp; }

        const u64* We2 = (const u64*)sA;
        const u64* Wa2 = (const u64*)sB;
#pragma unroll
        for (int i = 0; i < 64; i++) {
            u64 wep = We2[i * 32 + lane];
            u64 wap = Wa2[i * 32 + lane];
#pragma unroll
            for (int r = 0; r < 4; r++) {
                float kv = __shfl_sync(0xffffffffu, (i < 32) ? v0[r] : v1[r], i & 31);
                u64 kv2 = f2bc(kv);
                ea[r] = f2fma(kv2, wep, ea[r]);
                aa[r] = f2fma(kv2, wap, aa[r]);
            }
        }
#pragma unroll
        for (int r = 0; r < 4; r++) {
            float x0, x1;
            f2up(ea[r], x0, x1);
            *(float2*)&g_e[(size_t)(r0 + r) * 64 + 2 * lane] = make_float2(sigfast(x0), sigfast(x1));
            f2up(aa[r], x0, x1);
            *(float2*)&g_a[(size_t)(r0 + r) * 64 + 2 * lane] = make_float2(tanhfast(x0), tanhfast(x1));
        }
    }
}

// =====================================================================
// K2: gather tables into per-(b,t) streams, fold mask, pre-pack w pairs
// =====================================================================
__global__ void __launch_bounds__(256) k_gather(
    const int* __restrict__ question, const int* __restrict__ response,
    const float* __restrict__ mask)
{
    int w = threadIdx.x >> 5, lane = threadIdx.x & 31;
    int row = blockIdx.x * 8 + w;             // b*512 + t
    int q = question[row];
    int r = response[row];
    float mt = mask[row];
    int x = q + QNUM * r;

    float2 ev = *(const float2*)&g_e[(size_t)x * 64 + 2 * lane];
    float2 av = *(const float2*)&g_a[(size_t)x * 64 + 2 * lane];
    *(float2*)&g_em[(size_t)row * 64 + 2 * lane] = make_float2(-ev.x * mt, -ev.y * mt);
    *(float2*)&g_am[(size_t)row * 64 + 2 * lane] = make_float2(av.x * mt, av.y * mt);

    int b = row >> 9, t = row & 511;
#pragma unroll
    for (int jj = 0; jj < 2; jj++) {
        int j = lane + jj * 32;               // 0..63 = 8 groups x 8 slots
        int g = j >> 3, sl = j & 7;
        int np = (g < 2) ? 7 : 6;
        int m0 = (g < 2) ? 7 * g : 14 + 6 * (g - 2);
        float val = (sl < np) ? g_w[q * MNUM + m0 + sl] : 0.f;
        *(float2*)&g_w2f[(((size_t)(g * 64 + b)) * 512 + t) * 16 + 2 * sl] = make_float2(val, val);
    }
}

// =====================================================================
// K3: sequential scan. 128 CTAs = (64 b) x (2 splits of 4 m-groups).
// 4 warps per CTA -> 1 warp per SMSP (no issue-port sharing).
// Per 8-step block the 4 group partials are reduced in shared and one
// partial read stream per split is written to g_part.
// =====================================================================
__global__ void __launch_bounds__(128) k_scan(const float* __restrict__ Mv0)
{
    __shared__ __align__(16) u64 smw[3][4][8][8];   // [buf][g][step][slot]  6KB
    __shared__ __align__(16) u64 sme[3][8][32];     // [buf][step][dpair]    6KB
    __shared__ __align__(16) u64 sma[3][8][32];     //                       6KB
    __shared__ __align__(16) u64 stag[4][8][32];    // [g][step][dpair]      8KB

    int b     = blockIdx.x & 63;
    int split = blockIdx.x >> 6;
    int tid = threadIdx.x;
    int g = tid >> 5, lane = tid & 31;     // local group 0..3
    int gg = split * 4 + g;                // global group 0..7
    int np = (gg < 2) ? 7 : 6;
    int m0 = (gg < 2) ? 7 * gg : 14 + 6 * (gg - 2);

    u64 mv[7];
#pragma unroll
    for (int p = 0; p < 7; p++)
        mv[p] = (p < np) ? *(const u64*)&Mv0[(m0 + p) * 64 + 2 * lane] : 0ull;

    const char* wsrc  = (const char*)g_w2f + (size_t)(gg * 64 + b) * 32768 + (size_t)lane * 16;
    const char* emsrc = (const char*)g_em + (size_t)b * 131072 + (size_t)tid * 16;
    const char* amsrc = (const char*)g_am + (size_t)b * 131072 + (size_t)tid * 16;

    uint32_t swdst = (uint32_t)__cvta_generic_to_shared(&smw[0][0][0][0]) + g * 512 + lane * 16;
    uint32_t emdst = (uint32_t)__cvta_generic_to_shared(&sme[0][0][0]) + tid * 16;
    uint32_t amdst = (uint32_t)__cvta_generic_to_shared(&sma[0][0][0]) + tid * 16;

    auto issue = [&](int kb) {
        int buf = kb - (kb / 3) * 3;
        cpa16(swdst + buf * 2048, wsrc + (size_t)kb * 512);
        cpa16(emdst + buf * 2048, emsrc + (size_t)kb * 2048);
        cpa16(amdst + buf * 2048, amsrc + (size_t)kb * 2048);
    };

    issue(0); cpcommit();
    issue(1); cpcommit();
    issue(2); cpcommit();

    float* pbase = g_part + split * PART_STRIDE + (size_t)b * 511 * 64 + 2 * lane;

    for (int kb = 0; kb < 64; kb++) {
        cpwait<2>();
        __syncthreads();
        int buf = kb - (kb / 3) * 3;
        const u64* wr = &smw[buf][g][0][0];
#pragma unroll
        for (int s = 0; s < 8; s++) {
            u64 em2 = sme[buf][s][lane];
            u64 am2 = sma[buf][s][lane];
            u64 w0 = wr[s * 8 + 0], w1 = wr[s * 8 + 1], w2 = wr[s * 8 + 2],
                w3 = wr[s * 8 + 3], w4 = wr[s * 8 + 4], w5 = wr[s * 8 + 5],
                w6 = wr[s * 8 + 6];
            // read (state before this step's update)
            u64 p0 = f2mul(w0, mv[0]);
            u64 p1 = f2mul(w1, mv[1]);
            p0 = f2fma(w2, mv[2], p0);
            p1 = f2fma(w3, mv[3], p1);
            p0 = f2fma(w4, mv[4], p0);
            p1 = f2fma(w5, mv[5], p1);
            p0 = f2fma(w6, mv[6], p0);
            stag[g][s][lane] = f2add(p0, p1);
            // update: Mv += w * (mt*(a - e*Mv))
            u64 t0;
            t0 = f2fma(em2, mv[0], am2); mv[0] = f2fma(w0, t0, mv[0]);
            t0 = f2fma(em2, mv[1], am2); mv[1] = f2fma(w1, t0, mv[1]);
            t0 = f2fma(em2, mv[2], am2); mv[2] = f2fma(w2, t0, mv[2]);
            t0 = f2fma(em2, mv[3], am2); mv[3] = f2fma(w3, t0, mv[3]);
            t0 = f2fma(em2, mv[4], am2); mv[4] = f2fma(w4, t0, mv[4]);
            t0 = f2fma(em2, mv[5], am2); mv[5] = f2fma(w5, t0, mv[5]);
            t0 = f2fma(em2, mv[6], am2); mv[6] = f2fma(w6, t0, mv[6]);
        }
        __syncthreads();
        // warp g reduces steps 2g, 2g+1 across its CTA's 4 groups
#pragma unroll
        for (int ss = 0; ss < 2; ss++) {
            int so = g * 2 + ss;
            int t = kb * 8 + so;
            if (t > 0) {
                u64 a0 = f2add(stag[0][so][lane], stag[1][so][lane]);
                u64 a1 = f2add(stag[2][so][lane], stag[3][so][lane]);
                *(u64*)(pbase + (size_t)(t - 1) * 64) = f2add(a0, a1);
            }
        }
        if (kb + 3 < 64) issue(kb + 3);
        cpcommit();
    }
}

// =====================================================================
// K4: head as register-tiled GEMM. Block = 256 thr = 8 warps x 16 rows.
// Warp lanes form a 4x8 grid: tr (4) picks interleaved rows, tc (8) picks
// 4 d-pairs. Thread computes a 4-row x 4-dpair tile in 16 f32x2 regs.
// No shuffles in the mainloop; read rows staged in padded shared.
// =====================================================================
#define RSTR 68   // padded read row stride in floats

__global__ void __launch_bounds__(256) k_head(
    const int* __restrict__ question, const float* __restrict__ fW,
    const float* __restrict__ pW, const float* __restrict__ pb,
    float* __restrict__ out)
{
    __shared__ __align__(16) float sW[64 * 64];
    __shared__ __align__(16) float sread[128 * RSTR];
    __shared__ float spw[64];

    int tid = threadIdx.x;
    int warp = tid >> 5, lane = tid & 31;
    int tr = lane >> 3, tc = lane & 7;
    int rbase = blockIdx.x * 128;

    // fill fW1 (rows 0..63) and pW
    {
        const float4* src = (const float4*)fW;
        float4* dst = (float4*)sW;
        for (int idx = tid; idx < 1024; idx += 256) dst[idx] = src[idx];
        if (tid < 64) spw[tid] = pW[tid];
    }

    // stage read rows = part0 + part1 into padded shared
    {
        const float4* p0 = (const float4*)g_part;
        const float4* p1 = (const float4*)(g_part + PART_STRIDE);
#pragma unroll
        for (int k = 0; k < 8; k++) {
            int idx = k * 256 + tid;            // 2048 float4 elems
            int r = idx >> 4, c = idx & 15;
            int grow = min(rbase + r, BNUM * (TNUM - 1) - 1);
            float4 a = p0[(size_t)grow * 16 + c];
            float4 b4 = p1[(size_t)grow * 16 + c];
            float4 s;
            s.x = a.x + b4.x; s.y = a.y + b4.y; s.z = a.z + b4.z; s.w = a.w + b4.w;
            *(float4*)&sread[r * RSTR + c * 4] = s;
        }
    }

    // init accumulators from kf (q gathered per row)
    int myrow0 = rbase + warp * 16 + tr;        // rows myrow0 + 4*j
    u64 facc[4][4];
#pragma unroll
    for (int j = 0; j < 4; j++) {
        int row = min(myrow0 + 4 * j, BNUM * (TNUM - 1) - 1);
        int b = row / 511;
        int tp = row - b * 511;
        int q = question[b * 512 + tp + 1];
        const float4* kfp = (const float4*)&g_kf[(size_t)q * 64 + tc * 8];
        float4 A = kfp[0], B = kfp[1];
        facc[j][0] = f2pk(A.x, A.y);
        facc[j][1] = f2pk(A.z, A.w);
        facc[j][2] = f2pk(B.x, B.y);
        facc[j][3] = f2pk(B.z, B.w);
    }
    __syncthreads();

    const u64* W = (const u64*)sW;
    const float* sr = &sread[(warp * 16 + tr) * RSTR];
#pragma unroll 8
    for (int i = 0; i < 64; i++) {
        u64 w0 = W[i * 32 + tc * 4 + 0];
        u64 w1 = W[i * 32 + tc * 4 + 1];
        u64 w2 = W[i * 32 + tc * 4 + 2];
        u64 w3 = W[i * 32 + tc * 4 + 3];
#pragma unroll
        for (int j = 0; j < 4; j++) {
            u64 rb = f2bc(sr[j * 4 * RSTR + i]);
            facc[j][0] = f2fma(rb, w0, facc[j][0]);
            facc[j][1] = f2fma(rb, w1, facc[j][1]);
            facc[j][2] = f2fma(rb, w2, facc[j][2]);
            facc[j][3] = f2fma(rb, w3, facc[j][3]);
        }
    }

    float pwl[8];
#pragma unroll
    for (int k = 0; k < 8; k++) pwl[k] = spw[tc * 8 + k];
    float pbv = pb[0];

#pragma unroll
    for (int j = 0; j < 4; j++) {
        float s = 0.f;
#pragma unroll
        for (int p = 0; p < 4; p++) {
            float f0, f1;
            f2up(facc[j][p], f0, f1);
            s += tanhfast(f0) * pwl[2 * p] + tanhfast(f1) * pwl[2 * p + 1];
        }
        s += __shfl_xor_sync(0xffffffffu, s, 1);
        s += __shfl_xor_sync(0xffffffffu, s, 2);
        s += __shfl_xor_sync(0xffffffffu, s, 4);
        int row = myrow0 + 4 * j;
        if (tc == 0 && row < BNUM * (TNUM - 1)) out[row] = s + pbv;
    }
}

// =====================================================================
extern "C" void kernel_launch(void* const* d_in, const int* in_sizes, int n_in,
                              void* d_out, int out_size)
{
    const int*   question = (const int*)d_in[0];
    const int*   response = (const int*)d_in[1];
    const float* mask     = (const float*)d_in[2];
    const float* k_emb    = (const float*)d_in[3];
    const float* v_emb    = (const float*)d_in[4];
    const float* Mk       = (const float*)d_in[5];
    const float* Mv0      = (const float*)d_in[6];
    const float* e_W      = (const float*)d_in[7];
    const float* e_b      = (const float*)d_in[8];
    const float* a_W      = (const float*)d_in[9];
    const float* a_b      = (const float*)d_in[10];
    const float* f_W      = (const float*)d_in[11];
    const float* f_b      = (const float*)d_in[12];
    const float* p_W      = (const float*)d_in[13];
    const float* p_b      = (const float*)d_in[14];
    float* out = (float*)d_out;

    k_build<<<1875, 256>>>(k_emb, Mk, f_W, f_b, v_emb, e_W, e_b, a_W, a_b);
    k_gather<<<BNUM * TNUM / 8, 256>>>(question, response, mask);
    k_scan<<<128, 128>>>(Mv0);
    k_head<<<256, 256>>>(question, f_W, p_W, p_b, out);

    (void)in_sizes; (void)n_in; (void)out_size;
}

// round 7
// speedup vs baseline: 1.4607x; 1.0310x over previous
#include <cuda_runtime.h>
#include <cuda_bf16.h>
#include <stdint.h>

typedef unsigned long long u64;

#define QNUM 10000
#define DNUM 64
#define MNUM 50
#define BNUM 64
#define TNUM 512
#define PART_STRIDE ((size_t)BNUM * (TNUM - 1) * DNUM)   // floats per partial stream

// ---------------- static scratch (no allocations allowed) ----------------
__device__ float g_kf [QNUM * DNUM];                        // k-half of f-MLP + bias, per question id
__device__ __align__(16) float g_e  [2 * QNUM * DNUM];      // sigmoid erase per x id (raw)
__device__ __align__(16) float g_a  [2 * QNUM * DNUM];      // tanh add per x id (raw)
__device__ __align__(16) float g_wp [QNUM * 128];           // packed (w,w) pairs: [q][8 grp][8 slot]
__device__ __align__(16) float g_part[2 * PART_STRIDE];     // 2 partial read streams (split halves)

// ---------------- f32x2 helpers ----------------
__device__ __forceinline__ u64 f2pk(float a, float b) {
    u64 r; asm("mov.b64 %0,{%1,%2};" : "=l"(r) : "f"(a), "f"(b)); return r;
}
__device__ __forceinline__ u64 f2bc(float a) {
    u64 r; asm("mov.b64 %0,{%1,%1};" : "=l"(r) : "f"(a)); return r;
}
__device__ __forceinline__ void f2up(u64 v, float& a, float& b) {
    asm("mov.b64 {%0,%1},%2;" : "=f"(a), "=f"(b) : "l"(v));
}
__device__ __forceinline__ u64 f2fma(u64 a, u64 b, u64 c) {
    u64 d; asm("fma.rn.f32x2 %0,%1,%2,%3;" : "=l"(d) : "l"(a), "l"(b), "l"(c)); return d;
}
__device__ __forceinline__ u64 f2mul(u64 a, u64 b) {
    u64 d; asm("mul.rn.f32x2 %0,%1,%2;" : "=l"(d) : "l"(a), "l"(b)); return d;
}
__device__ __forceinline__ u64 f2add(u64 a, u64 b) {
    u64 d; asm("add.rn.f32x2 %0,%1,%2;" : "=l"(d) : "l"(a), "l"(b)); return d;
}

__device__ __forceinline__ float sigfast(float x) {
    return __fdividef(1.f, 1.f + __expf(-x));
}
__device__ __forceinline__ float tanhfast(float x) {
    x = fminf(fmaxf(x, -10.f), 10.f);
    float t = __expf(2.f * x);
    return (t - 1.f) * __fdividef(1.f, t + 1.f);
}

// ---------------- cp.async helpers ----------------
__device__ __forceinline__ void cpa16(uint32_t dst, const void* src) {
    asm volatile("cp.async.ca.shared.global [%0], [%1], 16;\n" :: "r"(dst), "l"(src));
}
__device__ __forceinline__ void cpcommit() { asm volatile("cp.async.commit_group;\n"); }
template <int N> __device__ __forceinline__ void cpwait() {
    asm volatile("cp.async.wait_group %0;\n" :: "n"(N));
}

// =====================================================================
// K1: merged precompute.
//   blocks [0,1250): per-question softmax weights (-> packed g_wp) + kf
//   blocks [1250,1875): e/a tables over 20000 v_emb rows (raw)
// =====================================================================
__global__ void __launch_bounds__(256) k_build(
    const float* __restrict__ k_emb, const float* __restrict__ Mk,
    const float* __restrict__ fW, const float* __restrict__ fb,
    const float* __restrict__ v_emb,
    const float* __restrict__ eW, const float* __restrict__ eb,
    const float* __restrict__ aW, const float* __restrict__ ab)
{
    __shared__ __align__(16) float sA[64 * 64];
    __shared__ __align__(16) float sB[64 * 64];
    __shared__ float sb0[64], sb1[64];
    __shared__ float swrow[8][52];

    int tid = threadIdx.x;
    int w = tid >> 5, lane = tid & 31;

    if (blockIdx.x < 1250) {
        // -------- wkf path --------
        for (int idx = tid; idx < 4096; idx += 256) {
            int i = idx >> 6, m = idx & 63;
            sA[idx] = (m < MNUM) ? Mk[m * 64 + i] : 0.f;   // MkT [i][m]
            sB[idx] = fW[64 * 64 + idx];                    // fW rows 64..127
        }
        if (tid < 64) sb0[tid] = fb[tid];
        __syncthreads();

        int q = blockIdx.x * 8 + w;

        float k0 = k_emb[q * 64 + lane];
        float k1 = k_emb[q * 64 + 32 + lane];

        float acc0 = 0.f, acc1 = 0.f;
#pragma unroll
        for (int i = 0; i < 64; i++) {
            float kv = __shfl_sync(0xffffffffu, (i < 32) ? k0 : k1, i & 31);
            acc0 += kv * sA[i * 64 + lane];
            acc1 += kv * sA[i * 64 + 32 + lane];
        }
        float v1 = (lane < 18) ? acc1 : -3.0e38f;
        float mx = fmaxf(acc0, v1);
#pragma unroll
        for (int d = 16; d >= 1; d >>= 1) mx = fmaxf(mx, __shfl_xor_sync(0xffffffffu, mx, d));
        float e0 = __expf(acc0 - mx);
        float e1 = (lane < 18) ? __expf(acc1 - mx) : 0.f;
        float sm = e0 + e1;
#pragma unroll
        for (int d = 16; d >= 1; d >>= 1) sm += __shfl_xor_sync(0xffffffffu, sm, d);
        float inv = __fdividef(1.f, sm);

        // stage w row, then write packed pair-duplicated zero-padded slots
        swrow[w][lane] = e0 * inv;
        if (lane < 18) swrow[w][32 + lane] = e1 * inv;
        __syncwarp();
#pragma unroll
        for (int jj = 0; jj < 2; jj++) {
            int j = lane + jj * 32;           // 0..63 = 8 groups x 8 slots
            int gg = j >> 3, sl = j & 7;
            int np = (gg < 2) ? 7 : 6;
            int m0 = (gg < 2) ? 7 * gg : 14 + 6 * (gg - 2);
            float val = (sl < np) ? swrow[w][m0 + sl] : 0.f;
            *(float2*)&g_wp[(size_t)q * 128 + 2 * j] = make_float2(val, val);
        }

        // kf = k @ fW2 + f_b
        u64 acc = f2pk(sb0[2 * lane], sb0[2 * lane + 1]);
        const u64* W2 = (const u64*)sB;
#pragma unroll
        for (int i = 0; i < 64; i++) {
            float kv = __shfl_sync(0xffffffffu, (i < 32) ? k0 : k1, i & 31);
            acc = f2fma(f2bc(kv), W2[i * 32 + lane], acc);
        }
        *(u64*)&g_kf[q * 64 + 2 * lane] = acc;
    } else {
        // -------- e/a path --------
        for (int idx = tid; idx < 4096; idx += 256) {
            sA[idx] = eW[idx];
            sB[idx] = aW[idx];
        }
        if (tid < 64) { sb0[tid] = eb[tid]; sb1[tid] = ab[tid]; }
        __syncthreads();

        int r0 = (blockIdx.x - 1250) * 32 + w * 4;

        float v0[4], v1[4];
#pragma unroll
        for (int r = 0; r < 4; r++) {
            v0[r] = v_emb[(r0 + r) * 64 + lane];
            v1[r] = v_emb[(r0 + r) * 64 + 32 + lane];
        }
        u64 ebp = f2pk(sb0[2 * lane], sb0[2 * lane + 1]);
        u64 abp = f2pk(sb1[2 * lane], sb1[2 * lane + 1]);
        u64 ea[4], aa[4];
#pragma unroll
        for (int r = 0; r < 4; r++) { ea[r] = ebp; aa[r] = abp; }

        const u64* We2 = (const u64*)sA;
        const u64* Wa2 = (const u64*)sB;
#pragma unroll
        for (int i = 0; i < 64; i++) {
            u64 wep = We2[i * 32 + lane];
            u64 wap = Wa2[i * 32 + lane];
#pragma unroll
            for (int r = 0; r < 4; r++) {
                float kv = __shfl_sync(0xffffffffu, (i < 32) ? v0[r] : v1[r], i & 31);
                u64 kv2 = f2bc(kv);
                ea[r] = f2fma(kv2, wep, ea[r]);
                aa[r] = f2fma(kv2, wap, aa[r]);
            }
        }
#pragma unroll
        for (int r = 0; r < 4; r++) {
            float x0, x1;
            f2up(ea[r], x0, x1);
            *(float2*)&g_e[(size_t)(r0 + r) * 64 + 2 * lane] = make_float2(sigfast(x0), sigfast(x1));
            f2up(aa[r], x0, x1);
            *(float2*)&g_a[(size_t)(r0 + r) * 64 + 2 * lane] = make_float2(tanhfast(x0), tanhfast(x1));
        }
    }
}

// =====================================================================
// K2: sequential scan with direct gather. 128 CTAs = (64 b) x (2 splits
// of 4 m-groups), 4 warps/CTA (1 per SMSP). cp.async pulls raw e/a rows
// and packed w straight from the id-indexed tables; mask folded in-loop.
// 16 steps per pipeline block, depth-3.
// =====================================================================
__global__ void __launch_bounds__(128) k_scan(
    const float* __restrict__ Mv0,
    const int* __restrict__ question, const int* __restrict__ response,
    const float* __restrict__ mask)
{
    __shared__ __align__(16) char sme[3][4096];     // raw e rows   12KB
    __shared__ __align__(16) char sma[3][4096];     // raw a rows   12KB
    __shared__ __align__(16) char smw[3][4096];     // packed w     12KB
    __shared__ __align__(16) u64 stag[4][16][32];   // group partials 16KB
    __shared__ int   sxoff[512];                    // x-id * 256 (byte off)
    __shared__ int   sqoff[512];                    // q*512 + split*256
    __shared__ float smask[512];

    int b     = blockIdx.x & 63;
    int split = blockIdx.x >> 6;
    int tid = threadIdx.x;
    int g = tid >> 5, lane = tid & 31;     // local group 0..3
    int gg = split * 4 + g;                // global group 0..7
    int np = (gg < 2) ? 7 : 6;
    int m0 = (gg < 2) ? 7 * gg : 14 + 6 * (gg - 2);

    // ---- meta preload: question/response/mask rows for this b ----
    {
        int4 qa = ((const int4*)(question + b * 512))[tid];
        int4 ra = ((const int4*)(response + b * 512))[tid];
        float4 ma = ((const float4*)(mask + b * 512))[tid];
        int base = tid * 4;
        int so = split * 256;
        sxoff[base + 0] = (qa.x + QNUM * ra.x) * 256;  sqoff[base + 0] = qa.x * 512 + so;
        sxoff[base + 1] = (qa.y + QNUM * ra.y) * 256;  sqoff[base + 1] = qa.y * 512 + so;
        sxoff[base + 2] = (qa.z + QNUM * ra.z) * 256;  sqoff[base + 2] = qa.z * 512 + so;
        sxoff[base + 3] = (qa.w + QNUM * ra.w) * 256;  sqoff[base + 3] = qa.w * 512 + so;
        smask[base + 0] = ma.x; smask[base + 1] = ma.y;
        smask[base + 2] = ma.z; smask[base + 3] = ma.w;
    }

    u64 mv[7];
#pragma unroll
    for (int p = 0; p < 7; p++)
        mv[p] = (p < np) ? *(const u64*)&Mv0[(m0 + p) * 64 + 2 * lane] : 0ull;

    __syncthreads();

    uint32_t sme_d = (uint32_t)__cvta_generic_to_shared(&sme[0][0]);
    uint32_t sma_d = (uint32_t)__cvta_generic_to_shared(&sma[0][0]);
    uint32_t smw_d = (uint32_t)__cvta_generic_to_shared(&smw[0][0]);
    const char* eB = (const char*)g_e;
    const char* aB = (const char*)g_a;
    const char* wB = (const char*)g_wp;

    auto issue = [&](int kb) {
        int buf = kb - (kb / 3) * 3;
        int t0 = kb * 16;
#pragma unroll
        for (int h = 0; h < 2; h++) {
            int c = tid + h * 128;            // 0..255 = 16 steps x 16 chunks
            int s = c >> 4, k16 = (c & 15) * 16;
            int xo = sxoff[t0 + s];
            int qo = sqoff[t0 + s];
            cpa16(sme_d + buf * 4096 + c * 16, eB + xo + k16);
            cpa16(sma_d + buf * 4096 + c * 16, aB + xo + k16);
            cpa16(smw_d + buf * 4096 + c * 16, wB + qo + k16);
        }
    };

    issue(0); cpcommit();
    issue(1); cpcommit();
    issue(2); cpcommit();

    float* pbase = g_part + split * PART_STRIDE + (size_t)b * 511 * 64 + 2 * lane;

    for (int kb = 0; kb < 32; kb++) {
        cpwait<2>();
        __syncthreads();
        int buf = kb - (kb / 3) * 3;
        const u64* eP = (const u64*)sme[buf];
        const u64* aP = (const u64*)sma[buf];
        const u64* wP = (const u64*)smw[buf];
#pragma unroll
        for (int s = 0; s < 16; s++) {
            float mt = smask[kb * 16 + s];
            u64 em2 = f2mul(eP[s * 32 + lane], f2bc(-mt));
            u64 am2 = f2mul(aP[s * 32 + lane], f2bc(mt));
            const u64* wr = wP + s * 32 + g * 8;
            u64 w0 = wr[0], w1 = wr[1], w2 = wr[2], w3 = wr[3],
                w4 = wr[4], w5 = wr[5], w6 = wr[6];
            // read (state before this step's update)
            u64 p0 = f2mul(w0, mv[0]);
            u64 p1 = f2mul(w1, mv[1]);
            p0 = f2fma(w2, mv[2], p0);
            p1 = f2fma(w3, mv[3], p1);
            p0 = f2fma(w4, mv[4], p0);
            p1 = f2fma(w5, mv[5], p1);
            p0 = f2fma(w6, mv[6], p0);
            stag[g][s][lane] = f2add(p0, p1);
            // update: Mv += w * (mt*(a - e*Mv))
            u64 t0;
            t0 = f2fma(em2, mv[0], am2); mv[0] = f2fma(w0, t0, mv[0]);
            t0 = f2fma(em2, mv[1], am2); mv[1] = f2fma(w1, t0, mv[1]);
            t0 = f2fma(em2, mv[2], am2); mv[2] = f2fma(w2, t0, mv[2]);
            t0 = f2fma(em2, mv[3], am2); mv[3] = f2fma(w3, t0, mv[3]);
            t0 = f2fma(em2, mv[4], am2); mv[4] = f2fma(w4, t0, mv[4]);
            t0 = f2fma(em2, mv[5], am2); mv[5] = f2fma(w5, t0, mv[5]);
            t0 = f2fma(em2, mv[6], am2); mv[6] = f2fma(w6, t0, mv[6]);
        }
        __syncthreads();
        // warp g reduces steps 4g..4g+3 across the CTA's 4 groups
#pragma unroll
        for (int ss = 0; ss < 4; ss++) {
            int so = g * 4 + ss;
            int t = kb * 16 + so;
            if (t > 0) {
                u64 a0 = f2add(stag[0][so][lane], stag[1][so][lane]);
                u64 a1 = f2add(stag[2][so][lane], stag[3][so][lane]);
                *(u64*)(pbase + (size_t)(t - 1) * 64) = f2add(a0, a1);
            }
        }
        if (kb + 3 < 32) issue(kb + 3);
        cpcommit();
    }
}

// =====================================================================
// K3: head as register-tiled GEMM. 64 rows/block, grid 511, smem ~34KB.
// Warp = 4x8 lanes; thread computes 2 rows x 4 dpairs. No shuffles in
// the mainloop; read rows (part0+part1) staged in padded shared.
// =====================================================================
#define RSTR 68   // padded read row stride in floats

__global__ void __launch_bounds__(256) k_head(
    const int* __restrict__ question, const float* __restrict__ fW,
    const float* __restrict__ pW, const float* __restrict__ pb,
    float* __restrict__ out)
{
    __shared__ __align__(16) float sW[64 * 64];
    __shared__ __align__(16) float sread[64 * RSTR];
    __shared__ float spw[64];

    int tid = threadIdx.x;
    int warp = tid >> 5, lane = tid & 31;
    int tr = lane >> 3, tc = lane & 7;
    int rbase = blockIdx.x * 64;

    // fill fW1 (rows 0..63) and pW
    {
        const float4* src = (const float4*)fW;
        float4* dst = (float4*)sW;
        for (int idx = tid; idx < 1024; idx += 256) dst[idx] = src[idx];
        if (tid < 64) spw[tid] = pW[tid];
    }

    // stage read rows = part0 + part1 into padded shared
    {
        const float4* p0 = (const float4*)g_part;
        const float4* p1 = (const float4*)(g_part + PART_STRIDE);
#pragma unroll
        for (int k = 0; k < 4; k++) {
            int idx = k * 256 + tid;            // 1024 float4 elems
            int r = idx >> 4, c = idx & 15;
            size_t grow = (size_t)(rbase + r) * 16 + c;
            float4 a = p0[grow];
            float4 b4 = p1[grow];
            float4 s;
            s.x = a.x + b4.x; s.y = a.y + b4.y; s.z = a.z + b4.z; s.w = a.w + b4.w;
            *(float4*)&sread[r * RSTR + c * 4] = s;
        }
    }

    // init accumulators from kf (q gathered per row)
    int myrow0 = rbase + warp * 8 + tr;        // rows myrow0 + 4*j, j<2
    u64 facc[2][4];
#pragma unroll
    for (int j = 0; j < 2; j++) {
        int row = myrow0 + 4 * j;
        int b = row / 511;
        int tp = row - b * 511;
        int q = question[b * 512 + tp + 1];
        const float4* kfp = (const float4*)&g_kf[(size_t)q * 64 + tc * 8];
        float4 A = kfp[0], B = kfp[1];
        facc[j][0] = f2pk(A.x, A.y);
        facc[j][1] = f2pk(A.z, A.w);
        facc[j][2] = f2pk(B.x, B.y);
        facc[j][3] = f2pk(B.z, B.w);
    }
    __syncthreads();

    const u64* W = (const u64*)sW;
    const float* sr = &sread[(warp * 8 + tr) * RSTR];
#pragma unroll 8
    for (int i = 0; i < 64; i++) {
        u64 w0 = W[i * 32 + tc * 4 + 0];
        u64 w1 = W[i * 32 + tc * 4 + 1];
        u64 w2 = W[i * 32 + tc * 4 + 2];
        u64 w3 = W[i * 32 + tc * 4 + 3];
#pragma unroll
        for (int j = 0; j < 2; j++) {
            u64 rb = f2bc(sr[j * 4 * RSTR + i]);
            facc[j][0] = f2fma(rb, w0, facc[j][0]);
            facc[j][1] = f2fma(rb, w1, facc[j][1]);
            facc[j][2] = f2fma(rb, w2, facc[j][2]);
            facc[j][3] = f2fma(rb, w3, facc[j][3]);
        }
    }

    float pwl[8];
#pragma unroll
    for (int k = 0; k < 8; k++) pwl[k] = spw[tc * 8 + k];
    float pbv = pb[0];

#pragma unroll
    for (int j = 0; j < 2; j++) {
        float s = 0.f;
#pragma unroll
        for (int p = 0; p < 4; p++) {
            float f0, f1;
            f2up(facc[j][p], f0, f1);
            s += tanhfast(f0) * pwl[2 * p] + tanhfast(f1) * pwl[2 * p + 1];
        }
        s += __shfl_xor_sync(0xffffffffu, s, 1);
        s += __shfl_xor_sync(0xffffffffu, s, 2);
        s += __shfl_xor_sync(0xffffffffu, s, 4);
        if (tc == 0) out[myrow0 + 4 * j] = s + pbv;
    }
}

// =====================================================================
extern "C" void kernel_launch(void* const* d_in, const int* in_sizes, int n_in,
                              void* d_out, int out_size)
{
    const int*   question = (const int*)d_in[0];
    const int*   response = (const int*)d_in[1];
    const float* mask     = (const float*)d_in[2];
    const float* k_emb    = (const float*)d_in[3];
    const float* v_emb    = (const float*)d_in[4];
    const float* Mk       = (const float*)d_in[5];
    const float* Mv0      = (const float*)d_in[6];
    const float* e_W      = (const float*)d_in[7];
    const float* e_b      = (const float*)d_in[8];
    const float* a_W      = (const float*)d_in[9];
    const float* a_b      = (const float*)d_in[10];
    const float* f_W      = (const float*)d_in[11];
    const float* f_b      = (const float*)d_in[12];
    const float* p_W      = (const float*)d_in[13];
    const float* p_b      = (const float*)d_in[14];
    float* out = (float*)d_out;

    k_build<<<1875, 256>>>(k_emb, Mk, f_W, f_b, v_emb, e_W, e_b, a_W, a_b);
    k_scan<<<128, 128>>>(Mv0, question, response, mask);
    k_head<<<511, 256>>>(question, f_W, p_W, p_b, out);

    (void)in_sizes; (void)n_in; (void)out_size;
}

// round 8
// speedup vs baseline: 1.5219x; 1.0419x over previous
#include <cuda_runtime.h>
#include <cuda_bf16.h>
#include <stdint.h>

typedef unsigned long long u64;

#define QNUM 10000
#define DNUM 64
#define MNUM 50
#define BNUM 64
#define TNUM 512
#define PART_STRIDE ((size_t)BNUM * (TNUM - 1) * DNUM)   // floats per partial stream

#define RB 96        // rows per build block
#define RSTRB 68     // padded staging stride (floats)
#define WKFB 105     // ceil(10000/96)
#define EAB 209      // ceil(20000/96)

// ---------------- static scratch (no allocations allowed) ----------------
__device__ float g_kf [QNUM * DNUM];                        // k-half of f-MLP + bias, per question id
__device__ __align__(16) float g_e  [2 * QNUM * DNUM];      // sigmoid erase per x id (raw)
__device__ __align__(16) float g_a  [2 * QNUM * DNUM];      // tanh add per x id (raw)
__device__ __align__(16) float g_wp [QNUM * 128];           // packed (w,w) pairs: pair j = w[m=j], j<50
__device__ __align__(16) float g_part[2 * PART_STRIDE];     // 2 partial read streams (split halves)

// ---------------- f32x2 helpers ----------------
__device__ __forceinline__ u64 f2pk(float a, float b) {
    u64 r; asm("mov.b64 %0,{%1,%2};" : "=l"(r) : "f"(a), "f"(b)); return r;
}
__device__ __forceinline__ u64 f2bc(float a) {
    u64 r; asm("mov.b64 %0,{%1,%1};" : "=l"(r) : "f"(a)); return r;
}
__device__ __forceinline__ void f2up(u64 v, float& a, float& b) {
    asm("mov.b64 {%0,%1},%2;" : "=f"(a), "=f"(b) : "l"(v));
}
__device__ __forceinline__ u64 f2fma(u64 a, u64 b, u64 c) {
    u64 d; asm("fma.rn.f32x2 %0,%1,%2,%3;" : "=l"(d) : "l"(a), "l"(b), "l"(c)); return d;
}
__device__ __forceinline__ u64 f2mul(u64 a, u64 b) {
    u64 d; asm("mul.rn.f32x2 %0,%1,%2;" : "=l"(d) : "l"(a), "l"(b)); return d;
}
__device__ __forceinline__ u64 f2add(u64 a, u64 b) {
    u64 d; asm("add.rn.f32x2 %0,%1,%2;" : "=l"(d) : "l"(a), "l"(b)); return d;
}

__device__ __forceinline__ float sigfast(float x) {
    return __fdividef(1.f, 1.f + __expf(-x));
}
__device__ __forceinline__ float tanhfast(float x) {
    x = fminf(fmaxf(x, -10.f), 10.f);
    float t = __expf(2.f * x);
    return (t - 1.f) * __fdividef(1.f, t + 1.f);
}

// ---------------- cp.async helpers ----------------
__device__ __forceinline__ void cpa16(uint32_t dst, const void* src) {
    asm volatile("cp.async.ca.shared.global [%0], [%1], 16;\n" :: "r"(dst), "l"(src));
}
__device__ __forceinline__ void cpcommit() { asm volatile("cp.async.commit_group;\n"); }
template <int N> __device__ __forceinline__ void cpwait() {
    asm volatile("cp.async.wait_group %0;\n" :: "n"(N));
}

// =====================================================================
// K1: precompute, shuffle-free register-tiled GEMMs.
//   blocks [0,WKFB): softmax weights (packed g_wp) + kf per question
//   blocks [WKFB,WKFB+EAB): e/a tables over 20000 v_emb rows
// Block stages 96 input rows (padded smem), weight mats processed
// sequentially (one 16KB mat resident). Thread = 3 rows x 4 dpairs.
// =====================================================================
__global__ void __launch_bounds__(256) k_build(
    const float* __restrict__ k_emb, const float* __restrict__ Mk,
    const float* __restrict__ fW, const float* __restrict__ fb,
    const float* __restrict__ v_emb,
    const float* __restrict__ eW, const float* __restrict__ eb,
    const float* __restrict__ aW, const float* __restrict__ ab)
{
    __shared__ __align__(16) float sV[RB * RSTRB];   // 26.1KB staged input rows
    __shared__ __align__(16) float sW[64 * 64];      // 16KB one weight matrix

    int tid = threadIdx.x;
    int warp = tid >> 5, lane = tid & 31;
    int tr = lane >> 3, tc = lane & 7;
    int lr0 = warp * 12 + tr;              // local rows lr0 + 4*j, j<3
    const u64* W = (const u64*)sW;

    if (blockIdx.x < WKFB) {
        // ================= wkf path =================
        int qbase = blockIdx.x * RB;
        for (int idx = tid; idx < RB * 16; idx += 256) {
            int r = idx >> 4, c = idx & 15;
            int q = min(qbase + r, QNUM - 1);
            *(float4*)&sV[r * RSTRB + c * 4] = ((const float4*)(k_emb + (size_t)q * 64))[c];
        }
        for (int idx = tid; idx < 4096; idx += 256) {
            int i = idx >> 6, m = idx & 63;
            sW[idx] = (m < MNUM) ? Mk[m * 64 + i] : 0.f;   // MkT [i][m], zero pad
        }
        __syncthreads();

        // ---- loop 1: logits = k @ MkT ----
        u64 acc[3][4];
#pragma unroll
        for (int j = 0; j < 3; j++)
#pragma unroll
            for (int p = 0; p < 4; p++) acc[j][p] = 0ull;

#pragma unroll 16
        for (int i = 0; i < 64; i++) {
            u64 w0 = W[i * 32 + tc * 4 + 0];
            u64 w1 = W[i * 32 + tc * 4 + 1];
            u64 w2 = W[i * 32 + tc * 4 + 2];
            u64 w3 = W[i * 32 + tc * 4 + 3];
#pragma unroll
            for (int j = 0; j < 3; j++) {
                u64 rb = f2bc(sV[(lr0 + 4 * j) * RSTRB + i]);
                acc[j][0] = f2fma(rb, w0, acc[j][0]);
                acc[j][1] = f2fma(rb, w1, acc[j][1]);
                acc[j][2] = f2fma(rb, w2, acc[j][2]);
                acc[j][3] = f2fma(rb, w3, acc[j][3]);
            }
        }

        // ---- softmax over m (thread owns m = tc*8..tc*8+7) ----
#pragma unroll
        for (int j = 0; j < 3; j++) {
            float l[8];
#pragma unroll
            for (int p = 0; p < 4; p++) f2up(acc[j][p], l[2 * p], l[2 * p + 1]);
#pragma unroll
            for (int k = 0; k < 8; k++)
                if (tc * 8 + k >= MNUM) l[k] = -3.0e38f;
            float mx = l[0];
#pragma unroll
            for (int k = 1; k < 8; k++) mx = fmaxf(mx, l[k]);
            mx = fmaxf(mx, __shfl_xor_sync(0xffffffffu, mx, 1));
            mx = fmaxf(mx, __shfl_xor_sync(0xffffffffu, mx, 2));
            mx = fmaxf(mx, __shfl_xor_sync(0xffffffffu, mx, 4));
            float sm = 0.f;
#pragma unroll
            for (int k = 0; k < 8; k++) { l[k] = __expf(l[k] - mx); sm += l[k]; }
            sm += __shfl_xor_sync(0xffffffffu, sm, 1);
            sm += __shfl_xor_sync(0xffffffffu, sm, 2);
            sm += __shfl_xor_sync(0xffffffffu, sm, 4);
            float inv = __fdividef(1.f, sm);
            int q = min(qbase + lr0 + 4 * j, QNUM - 1);
            float* wp = &g_wp[(size_t)q * 128 + tc * 16];
#pragma unroll
            for (int p = 0; p < 4; p++) {
                float a = l[2 * p] * inv, b = l[2 * p + 1] * inv;
                *(float4*)(wp + 4 * p) = make_float4(a, a, b, b);
            }
        }
        __syncthreads();

        // ---- loop 2: kf = k @ fW2 + fb ----
        for (int idx = tid; idx < 4096; idx += 256) sW[idx] = fW[4096 + idx];
        __syncthreads();

        u64 kacc[3][4];
        {
            const float4* fb4 = (const float4*)(fb + tc * 8);
            float4 A = fb4[0], B = fb4[1];
            u64 b0 = f2pk(A.x, A.y), b1 = f2pk(A.z, A.w);
            u64 b2 = f2pk(B.x, B.y), b3 = f2pk(B.z, B.w);
#pragma unroll
            for (int j = 0; j < 3; j++) {
                kacc[j][0] = b0; kacc[j][1] = b1; kacc[j][2] = b2; kacc[j][3] = b3;
            }
        }
#pragma unroll 16
        for (int i = 0; i < 64; i++) {
            u64 w0 = W[i * 32 + tc * 4 + 0];
            u64 w1 = W[i * 32 + tc * 4 + 1];
            u64 w2 = W[i * 32 + tc * 4 + 2];
            u64 w3 = W[i * 32 + tc * 4 + 3];
#pragma unroll
            for (int j = 0; j < 3; j++) {
                u64 rb = f2bc(sV[(lr0 + 4 * j) * RSTRB + i]);
                kacc[j][0] = f2fma(rb, w0, kacc[j][0]);
                kacc[j][1] = f2fma(rb, w1, kacc[j][1]);
                kacc[j][2] = f2fma(rb, w2, kacc[j][2]);
                kacc[j][3] = f2fma(rb, w3, kacc[j][3]);
            }
        }
#pragma unroll
        for (int j = 0; j < 3; j++) {
            int q = min(qbase + lr0 + 4 * j, QNUM - 1);
            u64* dst = (u64*)&g_kf[(size_t)q * 64 + tc * 8];
            dst[0] = kacc[j][0]; dst[1] = kacc[j][1];
            dst[2] = kacc[j][2]; dst[3] = kacc[j][3];
        }
    } else {
        // ================= e/a path =================
        int vbase = (blockIdx.x - WKFB) * RB;
        for (int idx = tid; idx < RB * 16; idx += 256) {
            int r = idx >> 4, c = idx & 15;
            int x = min(vbase + r, 2 * QNUM - 1);
            *(float4*)&sV[r * RSTRB + c * 4] = ((const float4*)(v_emb + (size_t)x * 64))[c];
        }
        for (int idx = tid; idx < 4096; idx += 256) sW[idx] = eW[idx];
        __syncthreads();

        // ---- loop 1: e = sigmoid(v @ eW + eb) ----
        u64 acc[3][4];
        {
            const float4* b4 = (const float4*)(eb + tc * 8);
            float4 A = b4[0], B = b4[1];
            u64 b0 = f2pk(A.x, A.y), b1 = f2pk(A.z, A.w);
            u64 b2 = f2pk(B.x, B.y), b3 = f2pk(B.z, B.w);
#pragma unroll
            for (int j = 0; j < 3; j++) {
                acc[j][0] = b0; acc[j][1] = b1; acc[j][2] = b2; acc[j][3] = b3;
            }
        }
#pragma unroll 16
        for (int i = 0; i < 64; i++) {
            u64 w0 = W[i * 32 + tc * 4 + 0];
            u64 w1 = W[i * 32 + tc * 4 + 1];
            u64 w2 = W[i * 32 + tc * 4 + 2];
            u64 w3 = W[i * 32 + tc * 4 + 3];
#pragma unroll
            for (int j = 0; j < 3; j++) {
                u64 rb = f2bc(sV[(lr0 + 4 * j) * RSTRB + i]);
                acc[j][0] = f2fma(rb, w0, acc[j][0]);
                acc[j][1] = f2fma(rb, w1, acc[j][1]);
                acc[j][2] = f2fma(rb, w2, acc[j][2]);
                acc[j][3] = f2fma(rb, w3, acc[j][3]);
            }
        }
#pragma unroll
        for (int j = 0; j < 3; j++) {
            int x = min(vbase + lr0 + 4 * j, 2 * QNUM - 1);
            float v0, v1, v2, v3, v4, v5, v6, v7;
            f2up(acc[j][0], v0, v1); f2up(acc[j][1], v2, v3);
            f2up(acc[j][2], v4, v5); f2up(acc[j][3], v6, v7);
            float4* dst = (float4*)&g_e[(size_t)x * 64 + tc * 8];
            dst[0] = make_float4(sigfast(v0), sigfast(v1), sigfast(v2), sigfast(v3));
            dst[1] = make_float4(sigfast(v4), sigfast(v5), sigfast(v6), sigfast(v7));
        }
        __syncthreads();

        // ---- loop 2: a = tanh(v @ aW + ab) ----
        for (int idx = tid; idx < 4096; idx += 256) sW[idx] = aW[idx];
        __syncthreads();
        {
            const float4* b4 = (const float4*)(ab + tc * 8);
            float4 A = b4[0], B = b4[1];
            u64 b0 = f2pk(A.x, A.y), b1 = f2pk(A.z, A.w);
            u64 b2 = f2pk(B.x, B.y), b3 = f2pk(B.z, B.w);
#pragma unroll
            for (int j = 0; j < 3; j++) {
                acc[j][0] = b0; acc[j][1] = b1; acc[j][2] = b2; acc[j][3] = b3;
            }
        }
#pragma unroll 16
        for (int i = 0; i < 64; i++) {
            u64 w0 = W[i * 32 + tc * 4 + 0];
            u64 w1 = W[i * 32 + tc * 4 + 1];
            u64 w2 = W[i * 32 + tc * 4 + 2];
            u64 w3 = W[i * 32 + tc * 4 + 3];
#pragma unroll
            for (int j = 0; j < 3; j++) {
                u64 rb = f2bc(sV[(lr0 + 4 * j) * RSTRB + i]);
                acc[j][0] = f2fma(rb, w0, acc[j][0]);
                acc[j][1] = f2fma(rb, w1, acc[j][1]);
                acc[j][2] = f2fma(rb, w2, acc[j][2]);
                acc[j][3] = f2fma(rb, w3, acc[j][3]);
            }
        }
#pragma unroll
        for (int j = 0; j < 3; j++) {
            int x = min(vbase + lr0 + 4 * j, 2 * QNUM - 1);
            float v0, v1, v2, v3, v4, v5, v6, v7;
            f2up(acc[j][0], v0, v1); f2up(acc[j][1], v2, v3);
            f2up(acc[j][2], v4, v5); f2up(acc[j][3], v6, v7);
            float4* dst = (float4*)&g_a[(size_t)x * 64 + tc * 8];
            dst[0] = make_float4(tanhfast(v0), tanhfast(v1), tanhfast(v2), tanhfast(v3));
            dst[1] = make_float4(tanhfast(v4), tanhfast(v5), tanhfast(v6), tanhfast(v7));
        }
    }
}

// =====================================================================
// K2: sequential scan with direct gather. 128 CTAs = (64 b) x (2 splits
// of 4 m-groups of 8), 4 warps/CTA. Uniform 8-slot groups (group g owns
// m in [8g, 8g+8), zeros beyond 50). 16 steps/pipeline block, depth-3.
// =====================================================================
__global__ void __launch_bounds__(128) k_scan(
    const float* __restrict__ Mv0,
    const int* __restrict__ question, const int* __restrict__ response,
    const float* __restrict__ mask)
{
    __shared__ __align__(16) char sme[3][4096];     // raw e rows   12KB
    __shared__ __align__(16) char sma[3][4096];     // raw a rows   12KB
    __shared__ __align__(16) char smw[3][4096];     // packed w     12KB
    __shared__ __align__(16) u64 stag[4][16][32];   // group partials 16KB
    __shared__ int   sxoff[512];                    // x-id * 256 (byte off)
    __shared__ int   sqoff[512];                    // q*512 + split*256
    __shared__ float smask[512];

    int b     = blockIdx.x & 63;
    int split = blockIdx.x >> 6;
    int tid = threadIdx.x;
    int g = tid >> 5, lane = tid & 31;     // local group 0..3
    int gg = split * 4 + g;                // global group 0..7
    int m0 = gg * 8;

    // ---- meta preload ----
    {
        int4 qa = ((const int4*)(question + b * 512))[tid];
        int4 ra = ((const int4*)(response + b * 512))[tid];
        float4 ma = ((const float4*)(mask + b * 512))[tid];
        int base = tid * 4;
        int so = split * 256;
        sxoff[base + 0] = (qa.x + QNUM * ra.x) * 256;  sqoff[base + 0] = qa.x * 512 + so;
        sxoff[base + 1] = (qa.y + QNUM * ra.y) * 256;  sqoff[base + 1] = qa.y * 512 + so;
        sxoff[base + 2] = (qa.z + QNUM * ra.z) * 256;  sqoff[base + 2] = qa.z * 512 + so;
        sxoff[base + 3] = (qa.w + QNUM * ra.w) * 256;  sqoff[base + 3] = qa.w * 512 + so;
        smask[base + 0] = ma.x; smask[base + 1] = ma.y;
        smask[base + 2] = ma.z; smask[base + 3] = ma.w;
    }

    u64 mv[8];
#pragma unroll
    for (int p = 0; p < 8; p++)
        mv[p] = (m0 + p < MNUM) ? *(const u64*)&Mv0[(m0 + p) * 64 + 2 * lane] : 0ull;

    __syncthreads();

    uint32_t sme_d = (uint32_t)__cvta_generic_to_shared(&sme[0][0]);
    uint32_t sma_d = (uint32_t)__cvta_generic_to_shared(&sma[0][0]);
    uint32_t smw_d = (uint32_t)__cvta_generic_to_shared(&smw[0][0]);
    const char* eB = (const char*)g_e;
    const char* aB = (const char*)g_a;
    const char* wB = (const char*)g_wp;

    auto issue = [&](int kb) {
        int buf = kb - (kb / 3) * 3;
        int t0 = kb * 16;
#pragma unroll
        for (int h = 0; h < 2; h++) {
            int c = tid + h * 128;            // 0..255 = 16 steps x 16 chunks
            int s = c >> 4, k16 = (c & 15) * 16;
            int xo = sxoff[t0 + s];
            int qo = sqoff[t0 + s];
            cpa16(sme_d + buf * 4096 + c * 16, eB + xo + k16);
            cpa16(sma_d + buf * 4096 + c * 16, aB + xo + k16);
            cpa16(smw_d + buf * 4096 + c * 16, wB + qo + k16);
        }
    };

    issue(0); cpcommit();
    issue(1); cpcommit();
    issue(2); cpcommit();

    float* pbase = g_part + split * PART_STRIDE + (size_t)b * 511 * 64 + 2 * lane;

    for (int kb = 0; kb < 32; kb++) {
        cpwait<2>();
        __syncthreads();
        int buf = kb - (kb / 3) * 3;
        const u64* eP = (const u64*)sme[buf];
        const u64* aP = (const u64*)sma[buf];
        const u64* wP = (const u64*)smw[buf];
#pragma unroll
        for (int s = 0; s < 16; s++) {
            float mt = smask[kb * 16 + s];
            u64 em2 = f2mul(eP[s * 32 + lane], f2bc(-mt));
            u64 am2 = f2mul(aP[s * 32 + lane], f2bc(mt));
            const u64* wr = wP + s * 32 + g * 8;
            u64 w0 = wr[0], w1 = wr[1], w2 = wr[2], w3 = wr[3],
                w4 = wr[4], w5 = wr[5], w6 = wr[6], w7 = wr[7];
            // read (state before this step's update)
            u64 p0 = f2mul(w0, mv[0]);
            u64 p1 = f2mul(w1, mv[1]);
            p0 = f2fma(w2, mv[2], p0);
            p1 = f2fma(w3, mv[3], p1);
            p0 = f2fma(w4, mv[4], p0);
            p1 = f2fma(w5, mv[5], p1);
            p0 = f2fma(w6, mv[6], p0);
            p1 = f2fma(w7, mv[7], p1);
            stag[g][s][lane] = f2add(p0, p1);
            // update: Mv += w * (mt*(a - e*Mv))
            u64 t0;
            t0 = f2fma(em2, mv[0], am2); mv[0] = f2fma(w0, t0, mv[0]);
            t0 = f2fma(em2, mv[1], am2); mv[1] = f2fma(w1, t0, mv[1]);
            t0 = f2fma(em2, mv[2], am2); mv[2] = f2fma(w2, t0, mv[2]);
            t0 = f2fma(em2, mv[3], am2); mv[3] = f2fma(w3, t0, mv[3]);
            t0 = f2fma(em2, mv[4], am2); mv[4] = f2fma(w4, t0, mv[4]);
            t0 = f2fma(em2, mv[5], am2); mv[5] = f2fma(w5, t0, mv[5]);
            t0 = f2fma(em2, mv[6], am2); mv[6] = f2fma(w6, t0, mv[6]);
            t0 = f2fma(em2, mv[7], am2); mv[7] = f2fma(w7, t0, mv[7]);
        }
        __syncthreads();
        // warp g reduces steps 4g..4g+3 across the CTA's 4 groups
#pragma unroll
        for (int ss = 0; ss < 4; ss++) {
            int so = g * 4 + ss;
            int t = kb * 16 + so;
            if (t > 0) {
                u64 a0 = f2add(stag[0][so][lane], stag[1][so][lane]);
                u64 a1 = f2add(stag[2][so][lane], stag[3][so][lane]);
                *(u64*)(pbase + (size_t)(t - 1) * 64) = f2add(a0, a1);
            }
        }
        if (kb + 3 < 32) issue(kb + 3);
        cpcommit();
    }
}

// =====================================================================
// K3: head as register-tiled GEMM. 64 rows/block, grid 511.
// =====================================================================
#define RSTR 68   // padded read row stride in floats

__global__ void __launch_bounds__(256) k_head(
    const int* __restrict__ question, const float* __restrict__ fW,
    const float* __restrict__ pW, const float* __restrict__ pb,
    float* __restrict__ out)
{
    __shared__ __align__(16) float sW[64 * 64];
    __shared__ __align__(16) float sread[64 * RSTR];
    __shared__ float spw[64];

    int tid = threadIdx.x;
    int warp = tid >> 5, lane = tid & 31;
    int tr = lane >> 3, tc = lane & 7;
    int rbase = blockIdx.x * 64;

    {
        const float4* src = (const float4*)fW;
        float4* dst = (float4*)sW;
        for (int idx = tid; idx < 1024; idx += 256) dst[idx] = src[idx];
        if (tid < 64) spw[tid] = pW[tid];
    }

    {
        const float4* p0 = (const float4*)g_part;
        const float4* p1 = (const float4*)(g_part + PART_STRIDE);
#pragma unroll
        for (int k = 0; k < 4; k++) {
            int idx = k * 256 + tid;
            int r = idx >> 4, c = idx & 15;
            size_t grow = (size_t)(rbase + r) * 16 + c;
            float4 a = p0[grow];
            float4 b4 = p1[grow];
            float4 s;
            s.x = a.x + b4.x; s.y = a.y + b4.y; s.z = a.z + b4.z; s.w = a.w + b4.w;
            *(float4*)&sread[r * RSTR + c * 4] = s;
        }
    }

    int myrow0 = rbase + warp * 8 + tr;        // rows myrow0 + 4*j, j<2
    u64 facc[2][4];
#pragma unroll
    for (int j = 0; j < 2; j++) {
        int row = myrow0 + 4 * j;
        int b = row / 511;
        int tp = row - b * 511;
        int q = question[b * 512 + tp + 1];
        const float4* kfp = (const float4*)&g_kf[(size_t)q * 64 + tc * 8];
        float4 A = kfp[0], B = kfp[1];
        facc[j][0] = f2pk(A.x, A.y);
        facc[j][1] = f2pk(A.z, A.w);
        facc[j][2] = f2pk(B.x, B.y);
        facc[j][3] = f2pk(B.z, B.w);
    }
    __syncthreads();

    const u64* W = (const u64*)sW;
    const float* sr = &sread[(warp * 8 + tr) * RSTR];
#pragma unroll 8
    for (int i = 0; i < 64; i++) {
        u64 w0 = W[i * 32 + tc * 4 + 0];
        u64 w1 = W[i * 32 + tc * 4 + 1];
        u64 w2 = W[i * 32 + tc * 4 + 2];
        u64 w3 = W[i * 32 + tc * 4 + 3];
#pragma unroll
        for (int j = 0; j < 2; j++) {
            u64 rb = f2bc(sr[j * 4 * RSTR + i]);
            facc[j][0] = f2fma(rb, w0, facc[j][0]);
            facc[j][1] = f2fma(rb, w1, facc[j][1]);
            facc[j][2] = f2fma(rb, w2, facc[j][2]);
            facc[j][3] = f2fma(rb, w3, facc[j][3]);
        }
    }

    float pwl[8];
#pragma unroll
    for (int k = 0; k < 8; k++) pwl[k] = spw[tc * 8 + k];
    float pbv = pb[0];

#pragma unroll
    for (int j = 0; j < 2; j++) {
        float s = 0.f;
#pragma unroll
        for (int p = 0; p < 4; p++) {
            float f0, f1;
            f2up(facc[j][p], f0, f1);
            s += tanhfast(f0) * pwl[2 * p] + tanhfast(f1) * pwl[2 * p + 1];
        }
        s += __shfl_xor_sync(0xffffffffu, s, 1);
        s += __shfl_xor_sync(0xffffffffu, s, 2);
        s += __shfl_xor_sync(0xffffffffu, s, 4);
        if (tc == 0) out[myrow0 + 4 * j] = s + pbv;
    }
}

// =====================================================================
extern "C" void kernel_launch(void* const* d_in, const int* in_sizes, int n_in,
                              void* d_out, int out_size)
{
    const int*   question = (const int*)d_in[0];
    const int*   response = (const int*)d_in[1];
    const float* mask     = (const float*)d_in[2];
    const float* k_emb    = (const float*)d_in[3];
    const float* v_emb    = (const float*)d_in[4];
    const float* Mk       = (const float*)d_in[5];
    const float* Mv0      = (const float*)d_in[6];
    const float* e_W      = (const float*)d_in[7];
    const float* e_b      = (const float*)d_in[8];
    const float* a_W      = (const float*)d_in[9];
    const float* a_b      = (const float*)d_in[10];
    const float* f_W      = (const float*)d_in[11];
    const float* f_b      = (const float*)d_in[12];
    const float* p_W      = (const float*)d_in[13];
    const float* p_b      = (const float*)d_in[14];
    float* out = (float*)d_out;

    k_build<<<WKFB + EAB, 256>>>(k_emb, Mk, f_W, f_b, v_emb, e_W, e_b, a_W, a_b);
    k_scan<<<128, 128>>>(Mv0, question, response, mask);
    k_head<<<511, 256>>>(question, f_W, p_W, p_b, out);

    (void)in_sizes; (void)n_in; (void)out_size;
}

// round 10
// speedup vs baseline: 1.8298x; 1.2023x over previous
#include <cuda_runtime.h>
#include <cuda_bf16.h>
#include <stdint.h>

typedef unsigned long long u64;

#define QNUM 10000
#define DNUM 64
#define MNUM 50
#define BNUM 64
#define TNUM 512
#define PART_STRIDE ((size_t)BNUM * (TNUM - 1) * DNUM)   // floats per partial stream

#define RB 48        // rows per build block
#define SVSTR 68     // padded staging stride (floats); 272B = 16B-aligned rows
#define WKFB 209     // ceil(10000/48)
#define EAB 417      // ceil(20000/48)

// ---------------- static scratch (no allocations allowed) ----------------
__device__ __align__(16) float g_kf [QNUM * DNUM];          // k-half of f-MLP + bias, per question id
__device__ __align__(16) float g_e  [2 * QNUM * DNUM];      // sigmoid erase per x id (raw)
__device__ __align__(16) float g_a  [2 * QNUM * DNUM];      // tanh add per x id (raw)
__device__ __align__(16) float g_wp [QNUM * 128];           // packed (w,w) pairs: pair j = w[m=j], j<50
__device__ __align__(16) float g_part[2 * PART_STRIDE];     // 2 partial read streams (split halves)

// ---------------- f32x2 helpers ----------------
__device__ __forceinline__ u64 f2pk(float a, float b) {
    u64 r; asm("mov.b64 %0,{%1,%2};" : "=l"(r) : "f"(a), "f"(b)); return r;
}
__device__ __forceinline__ u64 f2bc(float a) {
    u64 r; asm("mov.b64 %0,{%1,%1};" : "=l"(r) : "f"(a)); return r;
}
__device__ __forceinline__ void f2up(u64 v, float& a, float& b) {
    asm("mov.b64 {%0,%1},%2;" : "=f"(a), "=f"(b) : "l"(v));
}
__device__ __forceinline__ u64 f2fma(u64 a, u64 b, u64 c) {
    u64 d; asm("fma.rn.f32x2 %0,%1,%2,%3;" : "=l"(d) : "l"(a), "l"(b), "l"(c)); return d;
}
__device__ __forceinline__ u64 f2mul(u64 a, u64 b) {
    u64 d; asm("mul.rn.f32x2 %0,%1,%2;" : "=l"(d) : "l"(a), "l"(b)); return d;
}
__device__ __forceinline__ u64 f2add(u64 a, u64 b) {
    u64 d; asm("add.rn.f32x2 %0,%1,%2;" : "=l"(d) : "l"(a), "l"(b)); return d;
}

__device__ __forceinline__ float sigfast(float x) {
    return __fdividef(1.f, 1.f + __expf(-x));
}
__device__ __forceinline__ float tanhfast(float x) {
    x = fminf(fmaxf(x, -10.f), 10.f);
    float t = __expf(2.f * x);
    return (t - 1.f) * __fdividef(1.f, t + 1.f);
}

// ---------------- cp.async helpers ----------------
__device__ __forceinline__ void cpa16(uint32_t dst, const void* src) {
    asm volatile("cp.async.ca.shared.global [%0], [%1], 16;\n" :: "r"(dst), "l"(src));
}
__device__ __forceinline__ void cpcommit() { asm volatile("cp.async.commit_group;\n"); }
template <int N> __device__ __forceinline__ void cpwait() {
    asm volatile("cp.async.wait_group %0;\n" :: "n"(N));
}

// =====================================================================
// K1: precompute, fused dual-GEMM per block, 48 rows/CTA, 128 threads.
//   blocks [0,WKFB): logits->softmax (g_wp) + kf, per question id
//   blocks [WKFB,WKFB+EAB): e (sigmoid) + a (tanh) per v_emb row
// Thread = 3 rows x 4 strided d-pairs x 2 matrices (24 f32x2 accums).
// Both weight matrices resident in smem; single cp.async stage phase.
// =====================================================================
__global__ void __launch_bounds__(128) k_build(
    const float* __restrict__ k_emb, const float* __restrict__ Mk,
    const float* __restrict__ fW, const float* __restrict__ fb,
    const float* __restrict__ v_emb,
    const float* __restrict__ eW, const float* __restrict__ eb,
    const float* __restrict__ aW, const float* __restrict__ ab)
{
    __shared__ __align__(16) float sV[RB * SVSTR];   // 12.8KB staged input rows
    __shared__ __align__(16) u64 sW1[64 * 32];       // 16KB matrix 1 (pairs)
    __shared__ __align__(16) u64 sW2[64 * 32];       // 16KB matrix 2 (pairs)

    int tid = threadIdx.x;
    int warp = tid >> 5, lane = tid & 31;
    int tr = lane >> 3, tc = lane & 7;
    int lr0 = warp * 12 + tr;              // local rows lr0 + 4*j, j<3

    bool iswkf = blockIdx.x < WKFB;
    int rbase = iswkf ? blockIdx.x * RB : (blockIdx.x - WKFB) * RB;
    int nmax  = iswkf ? QNUM : 2 * QNUM;
    const float* src = iswkf ? k_emb : v_emb;

    uint32_t svd  = (uint32_t)__cvta_generic_to_shared(sV);
    uint32_t sw1d = (uint32_t)__cvta_generic_to_shared(sW1);
    uint32_t sw2d = (uint32_t)__cvta_generic_to_shared(sW2);

    // stage input rows (48 x 64 floats)
    for (int idx = tid; idx < RB * 16; idx += 128) {
        int r = idx >> 4, c = idx & 15;
        int row = min(rbase + r, nmax - 1);
        cpa16(svd + (r * SVSTR + c * 4) * 4, src + (size_t)row * 64 + c * 4);
    }
    // stage weight matrices
    if (iswkf) {
        for (int idx = tid; idx < 1024; idx += 128)
            cpa16(sw2d + idx * 16, fW + 4096 + idx * 4);     // fW rows 64..127
        // MkT pairs: sW1[i*32+j] = (Mk[2j][i], Mk[2j+1][i]), zero-padded m>=50
        for (int idx = tid; idx < 2048; idx += 128) {
            int j = idx & 31, i = idx >> 5;
            float a = (2 * j < MNUM) ? Mk[(2 * j) * 64 + i] : 0.f;
            float b = (2 * j + 1 < MNUM) ? Mk[(2 * j + 1) * 64 + i] : 0.f;
            sW1[i * 32 + j] = f2pk(a, b);
        }
    } else {
        for (int idx = tid; idx < 1024; idx += 128) {
            cpa16(sw1d + idx * 16, eW + idx * 4);
            cpa16(sw2d + idx * 16, aW + idx * 4);
        }
    }
    cpcommit();

    // init accumulators (strided pair j0 = 8p + tc); scalar bias loads
    u64 acc1[3][4], acc2[3][4];
    {
        const float* b2f = iswkf ? fb : ab;
#pragma unroll
        for (int p = 0; p < 4; p++) {
            int j0 = 8 * p + tc;
            u64 v1 = iswkf ? 0ull : f2pk(eb[2 * j0], eb[2 * j0 + 1]);
            u64 v2 = f2pk(b2f[2 * j0], b2f[2 * j0 + 1]);
#pragma unroll
            for (int j = 0; j < 3; j++) { acc1[j][p] = v1; acc2[j][p] = v2; }
        }
    }

    cpwait<0>();
    __syncthreads();

    // fused dual-GEMM mainloop
#pragma unroll 8
    for (int i = 0; i < 64; i++) {
        u64 w1[4], w2[4];
#pragma unroll
        for (int p = 0; p < 4; p++) {
            w1[p] = sW1[i * 32 + 8 * p + tc];
            w2[p] = sW2[i * 32 + 8 * p + tc];
        }
#pragma unroll
        for (int j = 0; j < 3; j++) {
            u64 rb = f2bc(sV[(lr0 + 4 * j) * SVSTR + i]);
            acc1[j][0] = f2fma(rb, w1[0], acc1[j][0]);
            acc2[j][0] = f2fma(rb, w2[0], acc2[j][0]);
            acc1[j][1] = f2fma(rb, w1[1], acc1[j][1]);
            acc2[j][1] = f2fma(rb, w2[1], acc2[j][1]);
            acc1[j][2] = f2fma(rb, w1[2], acc1[j][2]);
            acc2[j][2] = f2fma(rb, w2[2], acc2[j][2]);
            acc1[j][3] = f2fma(rb, w1[3], acc1[j][3]);
            acc2[j][3] = f2fma(rb, w2[3], acc2[j][3]);
        }
    }

    if (iswkf) {
        // softmax over m (thread owns m-pairs j0 = 8p+tc; pairs >=25 invalid)
#pragma unroll
        for (int j = 0; j < 3; j++) {
            int q = min(rbase + lr0 + 4 * j, QNUM - 1);
            float l[8];
#pragma unroll
            for (int p = 0; p < 4; p++) {
                f2up(acc1[j][p], l[2 * p], l[2 * p + 1]);
                if (8 * p + tc >= 25) { l[2 * p] = -3.0e38f; l[2 * p + 1] = -3.0e38f; }
            }
            float mx = l[0];
#pragma unroll
            for (int k = 1; k < 8; k++) mx = fmaxf(mx, l[k]);
            mx = fmaxf(mx, __shfl_xor_sync(0xffffffffu, mx, 1));
            mx = fmaxf(mx, __shfl_xor_sync(0xffffffffu, mx, 2));
            mx = fmaxf(mx, __shfl_xor_sync(0xffffffffu, mx, 4));
            float sm = 0.f;
#pragma unroll
            for (int k = 0; k < 8; k++) { l[k] = __expf(l[k] - mx); sm += l[k]; }
            sm += __shfl_xor_sync(0xffffffffu, sm, 1);
            sm += __shfl_xor_sync(0xffffffffu, sm, 2);
            sm += __shfl_xor_sync(0xffffffffu, sm, 4);
            float inv = __fdividef(1.f, sm);
            float* wp = g_wp + (size_t)q * 128;
            u64* kfd = (u64*)(g_kf + (size_t)q * 64);
#pragma unroll
            for (int p = 0; p < 4; p++) {
                int j0 = 8 * p + tc;
                float va = l[2 * p] * inv, vb = l[2 * p + 1] * inv;
                *(float4*)(wp + 4 * j0) = make_float4(va, va, vb, vb);
                kfd[j0] = acc2[j][p];
            }
        }
    } else {
        // e = sigmoid(acc1), a = tanh(acc2)
#pragma unroll
        for (int j = 0; j < 3; j++) {
            int x = min(rbase + lr0 + 4 * j, 2 * QNUM - 1);
            u64* ed = (u64*)(g_e + (size_t)x * 64);
            u64* ad = (u64*)(g_a + (size_t)x * 64);
#pragma unroll
            for (int p = 0; p < 4; p++) {
                int j0 = 8 * p + tc;
                float x0, x1;
                f2up(acc1[j][p], x0, x1);
                ed[j0] = f2pk(sigfast(x0), sigfast(x1));
                f2up(acc2[j][p], x0, x1);
                ad[j0] = f2pk(tanhfast(x0), tanhfast(x1));
            }
        }
    }
}

// =====================================================================
// K2: sequential scan with direct gather. 128 CTAs = (64 b) x (2 splits
// of 4 m-groups of 8), 4 warps/CTA. Uniform 8-slot groups. 16 steps per
// pipeline block, depth-3 cp.async.
// =====================================================================
__global__ void __launch_bounds__(128) k_scan(
    const float* __restrict__ Mv0,
    const int* __restrict__ question, const int* __restrict__ response,
    const float* __restrict__ mask)
{
    __shared__ __align__(16) char sme[3][4096];     // raw e rows   12KB
    __shared__ __align__(16) char sma[3][4096];     // raw a rows   12KB
    __shared__ __align__(16) char smw[3][4096];     // packed w     12KB
    __shared__ __align__(16) u64 stag[4][16][32];   // group partials 16KB
    __shared__ int   sxoff[512];                    // x-id * 256 (byte off)
    __shared__ int   sqoff[512];                    // q*512 + split*256
    __shared__ float smask[512];

    int b     = blockIdx.x & 63;
    int split = blockIdx.x >> 6;
    int tid = threadIdx.x;
    int g = tid >> 5, lane = tid & 31;     // local group 0..3
    int gg = split * 4 + g;                // global group 0..7
    int m0 = gg * 8;

    // ---- meta preload ----
    {
        int4 qa = ((const int4*)(question + b * 512))[tid];
        int4 ra = ((const int4*)(response + b * 512))[tid];
        float4 ma = ((const float4*)(mask + b * 512))[tid];
        int base = tid * 4;
        int so = split * 256;
        sxoff[base + 0] = (qa.x + QNUM * ra.x) * 256;  sqoff[base + 0] = qa.x * 512 + so;
        sxoff[base + 1] = (qa.y + QNUM * ra.y) * 256;  sqoff[base + 1] = qa.y * 512 + so;
        sxoff[base + 2] = (qa.z + QNUM * ra.z) * 256;  sqoff[base + 2] = qa.z * 512 + so;
        sxoff[base + 3] = (qa.w + QNUM * ra.w) * 256;  sqoff[base + 3] = qa.w * 512 + so;
        smask[base + 0] = ma.x; smask[base + 1] = ma.y;
        smask[base + 2] = ma.z; smask[base + 3] = ma.w;
    }

    u64 mv[8];
#pragma unroll
    for (int p = 0; p < 8; p++)
        mv[p] = (m0 + p < MNUM) ? *(const u64*)&Mv0[(m0 + p) * 64 + 2 * lane] : 0ull;

    __syncthreads();

    uint32_t sme_d = (uint32_t)__cvta_generic_to_shared(&sme[0][0]);
    uint32_t sma_d = (uint32_t)__cvta_generic_to_shared(&sma[0][0]);
    uint32_t smw_d = (uint32_t)__cvta_generic_to_shared(&smw[0][0]);
    const char* eB = (const char*)g_e;
    const char* aB = (const char*)g_a;
    const char* wB = (const char*)g_wp;

    auto issue = [&](int kb) {
        int buf = kb - (kb / 3) * 3;
        int t0 = kb * 16;
#pragma unroll
        for (int h = 0; h < 2; h++) {
            int c = tid + h * 128;            // 0..255 = 16 steps x 16 chunks
            int s = c >> 4, k16 = (c & 15) * 16;
            int xo = sxoff[t0 + s];
            int qo = sqoff[t0 + s];
            cpa16(sme_d + buf * 4096 + c * 16, eB + xo + k16);
            cpa16(sma_d + buf * 4096 + c * 16, aB + xo + k16);
            cpa16(smw_d + buf * 4096 + c * 16, wB + qo + k16);
        }
    };

    issue(0); cpcommit();
    issue(1); cpcommit();
    issue(2); cpcommit();

    float* pbase = g_part + split * PART_STRIDE + (size_t)b * 511 * 64 + 2 * lane;

    for (int kb = 0; kb < 32; kb++) {
        cpwait<2>();
        __syncthreads();
        int buf = kb - (kb / 3) * 3;
        const u64* eP = (const u64*)sme[buf];
        const u64* aP = (const u64*)sma[buf];
        const u64* wP = (const u64*)smw[buf];
#pragma unroll
        for (int s = 0; s < 16; s++) {
            float mt = smask[kb * 16 + s];
            u64 em2 = f2mul(eP[s * 32 + lane], f2bc(-mt));
            u64 am2 = f2mul(aP[s * 32 + lane], f2bc(mt));
            const u64* wr = wP + s * 32 + g * 8;
            u64 w0 = wr[0], w1 = wr[1], w2 = wr[2], w3 = wr[3],
                w4 = wr[4], w5 = wr[5], w6 = wr[6], w7 = wr[7];
            // read (state before this step's update)
            u64 p0 = f2mul(w0, mv[0]);
            u64 p1 = f2mul(w1, mv[1]);
            p0 = f2fma(w2, mv[2], p0);
            p1 = f2fma(w3, mv[3], p1);
            p0 = f2fma(w4, mv[4], p0);
            p1 = f2fma(w5, mv[5], p1);
            p0 = f2fma(w6, mv[6], p0);
            p1 = f2fma(w7, mv[7], p1);
            stag[g][s][lane] = f2add(p0, p1);
            // update: Mv += w * (mt*(a - e*Mv))
            u64 t0;
            t0 = f2fma(em2, mv[0], am2); mv[0] = f2fma(w0, t0, mv[0]);
            t0 = f2fma(em2, mv[1], am2); mv[1] = f2fma(w1, t0, mv[1]);
            t0 = f2fma(em2, mv[2], am2); mv[2] = f2fma(w2, t0, mv[2]);
            t0 = f2fma(em2, mv[3], am2); mv[3] = f2fma(w3, t0, mv[3]);
            t0 = f2fma(em2, mv[4], am2); mv[4] = f2fma(w4, t0, mv[4]);
            t0 = f2fma(em2, mv[5], am2); mv[5] = f2fma(w5, t0, mv[5]);
            t0 = f2fma(em2, mv[6], am2); mv[6] = f2fma(w6, t0, mv[6]);
            t0 = f2fma(em2, mv[7], am2); mv[7] = f2fma(w7, t0, mv[7]);
        }
        __syncthreads();
        // warp g reduces steps 4g..4g+3 across the CTA's 4 groups
#pragma unroll
        for (int ss = 0; ss < 4; ss++) {
            int so = g * 4 + ss;
            int t = kb * 16 + so;
            if (t > 0) {
                u64 a0 = f2add(stag[0][so][lane], stag[1][so][lane]);
                u64 a1 = f2add(stag[2][so][lane], stag[3][so][lane]);
                *(u64*)(pbase + (size_t)(t - 1) * 64) = f2add(a0, a1);
            }
        }
        if (kb + 3 < 32) issue(kb + 3);
        cpcommit();
    }
}

// =====================================================================
// K3: head as register-tiled GEMM. 64 rows/block, grid 511.
// =====================================================================
#define RSTR 68   // padded read row stride in floats

__global__ void __launch_bounds__(256) k_head(
    const int* __restrict__ question, const float* __restrict__ fW,
    const float* __restrict__ pW, const float* __restrict__ pb,
    float* __restrict__ out)
{
    __shared__ __align__(16) float sW[64 * 64];
    __shared__ __align__(16) float sread[64 * RSTR];
    __shared__ float spw[64];

    int tid = threadIdx.x;
    int warp = tid >> 5, lane = tid & 31;
    int tr = lane >> 3, tc = lane & 7;
    int rbase = blockIdx.x * 64;

    {
        const float4* src = (const float4*)fW;
        float4* dst = (float4*)sW;
        for (int idx = tid; idx < 1024; idx += 256) dst[idx] = src[idx];
        if (tid < 64) spw[tid] = pW[tid];
    }

    {
        const float4* p0 = (const float4*)g_part;
        const float4* p1 = (const float4*)(g_part + PART_STRIDE);
#pragma unroll
        for (int k = 0; k < 4; k++) {
            int idx = k * 256 + tid;
            int r = idx >> 4, c = idx & 15;
            size_t grow = (size_t)(rbase + r) * 16 + c;
            float4 a = p0[grow];
            float4 b4 = p1[grow];
            float4 s;
            s.x = a.x + b4.x; s.y = a.y + b4.y; s.z = a.z + b4.z; s.w = a.w + b4.w;
            *(float4*)&sread[r * RSTR + c * 4] = s;
        }
    }

    int myrow0 = rbase + warp * 8 + tr;        // rows myrow0 + 4*j, j<2
    u64 facc[2][4];
#pragma unroll
    for (int j = 0; j < 2; j++) {
        int row = myrow0 + 4 * j;
        int b = row / 511;
        int tp = row - b * 511;
        int q = question[b * 512 + tp + 1];
        const float4* kfp = (const float4*)&g_kf[(size_t)q * 64 + tc * 8];
        float4 A = kfp[0], B = kfp[1];
        facc[j][0] = f2pk(A.x, A.y);
        facc[j][1] = f2pk(A.z, A.w);
        facc[j][2] = f2pk(B.x, B.y);
        facc[j][3] = f2pk(B.z, B.w);
    }
    __syncthreads();

    const u64* W = (const u64*)sW;
    const float* sr = &sread[(warp * 8 + tr) * RSTR];
#pragma unroll 8
    for (int i = 0; i < 64; i++) {
        u64 w0 = W[i * 32 + tc * 4 + 0];
        u64 w1 = W[i * 32 + tc * 4 + 1];
        u64 w2 = W[i * 32 + tc * 4 + 2];
        u64 w3 = W[i * 32 + tc * 4 + 3];
#pragma unroll
        for (int j = 0; j < 2; j++) {
            u64 rb = f2bc(sr[j * 4 * RSTR + i]);
            facc[j][0] = f2fma(rb, w0, facc[j][0]);
            facc[j][1] = f2fma(rb, w1, facc[j][1]);
            facc[j][2] = f2fma(rb, w2, facc[j][2]);
            facc[j][3] = f2fma(rb, w3, facc[j][3]);
        }
    }

    float pwl[8];
#pragma unroll
    for (int k = 0; k < 8; k++) pwl[k] = spw[tc * 8 + k];
    float pbv = pb[0];

#pragma unroll
    for (int j = 0; j < 2; j++) {
        float s = 0.f;
#pragma unroll
        for (int p = 0; p < 4; p++) {
            float f0, f1;
            f2up(facc[j][p], f0, f1);
            s += tanhfast(f0) * pwl[2 * p] + tanhfast(f1) * pwl[2 * p + 1];
        }
        s += __shfl_xor_sync(0xffffffffu, s, 1);
        s += __shfl_xor_sync(0xffffffffu, s, 2);
        s += __shfl_xor_sync(0xffffffffu, s, 4);
        if (tc == 0) out[myrow0 + 4 * j] = s + pbv;
    }
}

// =====================================================================
extern "C" void kernel_launch(void* const* d_in, const int* in_sizes, int n_in,
                              void* d_out, int out_size)
{
    const int*   question = (const int*)d_in[0];
    const int*   response = (const int*)d_in[1];
    const float* mask     = (const float*)d_in[2];
    const float* k_emb    = (const float*)d_in[3];
    const float* v_emb    = (const float*)d_in[4];
    const float* Mk       = (const float*)d_in[5];
    const float* Mv0      = (const float*)d_in[6];
    const float* e_W      = (const float*)d_in[7];
    const float* e_b      = (const float*)d_in[8];
    const float* a_W      = (const float*)d_in[9];
    const float* a_b      = (const float*)d_in[10];
    const float* f_W      = (const float*)d_in[11];
    const float* f_b      = (const float*)d_in[12];
    const float* p_W      = (const float*)d_in[13];
    const float* p_b      = (const float*)d_in[14];
    float* out = (float*)d_out;

    k_build<<<WKFB + EAB, 128>>>(k_emb, Mk, f_W, f_b, v_emb, e_W, e_b, a_W, a_b);
    k_scan<<<128, 128>>>(Mv0, question, response, mask);
    k_head<<<511, 256>>>(question, f_W, p_W, p_b, out);

    (void)in_sizes; (void)n_in; (void)out_size;
}